// round 1
// baseline (speedup 1.0000x reference)
#include <cuda_runtime.h>
#include <cstdint>
#include <cstdio>

#define BB 8
#define CC_ 128
#define HH 192
#define WW 192
#define HW (HH*WW)
#define CHW (CC_*HW)
#define TOT (BB*CHW)
#define KK 1152            // C*9
#define EPSV 1e-5f
#define NORM_SCALE 0.1816f
#define STAT_N (BB*4*(HH/2)*(WW/2))   // 294912

// ---------------- scratch (device globals; no allocations allowed) ------------
__device__ float g_a1[TOT];
__device__ float g_a2[TOT];
__device__ float g_a3[TOT];
__device__ float g_av[TOT];
__device__ float g_wt[3][KK*CC_];     // transposed static weights: [(c*9+k)][o]
__device__ float g_attn[BB*CC_*KK];   // [b][o][i*9+h*3+w]
__device__ float g_kern[(size_t)BB*KK*CC_];   // [b][(i*9+k)][o]
__device__ float g_sum[CC_];
__device__ float g_sumsq[CC_];
__device__ float g_mean[CC_];
__device__ float g_inv[CC_];

// ---------------- packed fp32x2 fma (sm_100+) --------------------------------
__device__ __forceinline__ unsigned long long ffma2(unsigned long long a,
                                                    unsigned long long b,
                                                    unsigned long long c) {
    unsigned long long d;
    asm("fma.rn.f32x2 %0, %1, %2, %3;" : "=l"(d) : "l"(a), "l"(b), "l"(c));
    return d;
}

// ---------------- zero accumulators ------------------------------------------
__global__ void zero_kernel() {
    int n = BB*CC_*KK;
    for (int i = blockIdx.x*blockDim.x + threadIdx.x; i < n; i += gridDim.x*blockDim.x)
        g_attn[i] = 0.f;
    if (blockIdx.x == 0 && threadIdx.x < CC_) {
        g_sum[threadIdx.x] = 0.f;
        g_sumsq[threadIdx.x] = 0.f;
    }
}

// ---------------- transpose static conv weights to [(c*9+k)][o] --------------
__global__ void wtrans_kernel(const float* __restrict__ w1,
                              const float* __restrict__ w2,
                              const float* __restrict__ w3) {
    const float* w = (blockIdx.y == 0) ? w1 : (blockIdx.y == 1) ? w2 : w3;
    for (int e = blockIdx.x*blockDim.x + threadIdx.x; e < KK*CC_; e += gridDim.x*blockDim.x) {
        int r = e / CC_, o = e % CC_;
        g_wt[blockIdx.y][e] = w[(size_t)o*KK + r];
    }
}

// ---------------- direct 3x3 conv (SAME, cross-correlation), fp32x2 ----------
// tile per block: 64 out-channels x (4 rows x 16 cols). 256 threads.
// thread (tx=col, ty -> 4 o's). accumulators are f32x2 pairs along o.
__global__ __launch_bounds__(256) void conv3x3_kernel(const float* __restrict__ in,
                                                      const float* __restrict__ wt,
                                                      float* __restrict__ out,
                                                      long wstride) {
    __shared__ float  Wsm[36][64];       // [ic*9+k][o]  9216 B
    __shared__ float2 Xsm[4][6][18];     // duplicated x  3456 B
    const int b = blockIdx.z;
    const int obase = blockIdx.y * 64;
    const int tiley = blockIdx.x / (WW/16);
    const int tilex = blockIdx.x % (WW/16);
    const int y0 = tiley*4, x0 = tilex*16;
    const float* inb = in + (size_t)b*CHW;
    const float* wtb = wt + (size_t)b*wstride;
    const int tid = threadIdx.x;
    const int tx = tid & 15, ty = tid >> 4;

    unsigned long long acc[2][4];
#pragma unroll
    for (int j = 0; j < 2; j++)
#pragma unroll
        for (int r = 0; r < 4; r++) acc[j][r] = 0ull;

    for (int ic0 = 0; ic0 < CC_; ic0 += 4) {
        __syncthreads();
#pragma unroll
        for (int e = tid; e < 36*64; e += 256) {
            int r = e >> 6, c = e & 63;
            Wsm[r][c] = wtb[(size_t)(ic0*9 + r)*CC_ + obase + c];
        }
        for (int e = tid; e < 432; e += 256) {
            int ic = e / 108; int rem = e - ic*108;
            int r = rem / 18; int cc = rem - r*18;
            int gy = y0 - 1 + r, gx = x0 - 1 + cc;
            float v = 0.f;
            if ((unsigned)gy < HH && (unsigned)gx < WW)
                v = inb[(size_t)(ic0 + ic)*HW + gy*WW + gx];
            Xsm[ic][r][cc] = make_float2(v, v);
        }
        __syncthreads();
#pragma unroll
        for (int ic = 0; ic < 4; ic++) {
#pragma unroll
            for (int ky = 0; ky < 3; ky++) {
#pragma unroll
                for (int kx = 0; kx < 3; kx++) {
                    const float* wp = &Wsm[ic*9 + ky*3 + kx][ty << 2];
                    unsigned long long w01 = *(const unsigned long long*)(wp);
                    unsigned long long w23 = *(const unsigned long long*)(wp + 2);
#pragma unroll
                    for (int r = 0; r < 4; r++) {
                        unsigned long long xv =
                            *(const unsigned long long*)&Xsm[ic][r + ky][tx + kx];
                        acc[0][r] = ffma2(w01, xv, acc[0][r]);
                        acc[1][r] = ffma2(w23, xv, acc[1][r]);
                    }
                }
            }
        }
    }
    float* outb = out + (size_t)b*CHW;
#pragma unroll
    for (int j = 0; j < 2; j++) {
#pragma unroll
        for (int r = 0; r < 4; r++) {
            unsigned long long a = acc[j][r];
            float lo = __uint_as_float((unsigned)a);
            float hi = __uint_as_float((unsigned)(a >> 32));
            int o = obase + (ty << 2) + j*2;
            size_t base = (size_t)o*HW + (size_t)(y0 + r)*WW + x0 + tx;
            outb[base]      = lo;
            outb[base + HW] = hi;
        }
    }
}

// ---------------- attention correlation GEMM ---------------------------------
// attn[b,h,w,i,o] = sum over positions with y%3==h, x%3==w of a1[i,pos]*a2[o,pos]
// block: 32 i x 64 o tile, one batch, one 24-row y-chunk. parity via unrolling.
__global__ __launch_bounds__(256) void attn_gemm_kernel() {
    __shared__ float a1s[96][34];   // [xcol][i]
    __shared__ float a2s[64][97];   // [o][xcol]
    const int ib = blockIdx.x * 32;
    const int ob = blockIdx.y * 64;
    const int b  = blockIdx.z >> 3;
    const int yb = (blockIdx.z & 7) * 24;
    const int tid = threadIdx.x;
    const int o0 = (tid & 15) * 4;
    const int i0 = (tid >> 4) * 2;
    const float* a1b = g_a1 + (size_t)b*CHW;
    const float* a2b = g_a2 + (size_t)b*CHW;

    float acc[3][3][2][4];
#pragma unroll
    for (int h = 0; h < 3; h++)
#pragma unroll
        for (int w = 0; w < 3; w++)
#pragma unroll
            for (int ii = 0; ii < 2; ii++)
#pragma unroll
                for (int j = 0; j < 4; j++) acc[h][w][ii][j] = 0.f;

    for (int y3 = 0; y3 < 8; y3++) {
#pragma unroll
        for (int h = 0; h < 3; h++) {
            const int y = yb + y3*3 + h;
#pragma unroll
            for (int xc = 0; xc < 192; xc += 96) {
                __syncthreads();
                for (int e = tid; e < 32*96; e += 256) {
                    int ii = e / 96, cc = e - ii*96;
                    a1s[cc][ii] = a1b[(size_t)(ib + ii)*HW + y*WW + xc + cc];
                }
                for (int e = tid; e < 64*96; e += 256) {
                    int oo = e / 96, cc = e - oo*96;
                    a2s[oo][cc] = a2b[(size_t)(ob + oo)*HW + y*WW + xc + cc];
                }
                __syncthreads();
#pragma unroll 2
                for (int x3 = 0; x3 < 32; x3++) {
#pragma unroll
                    for (int w = 0; w < 3; w++) {
                        const int cc = x3*3 + w;
                        float ai0 = a1s[cc][i0];
                        float ai1 = a1s[cc][i0 + 1];
#pragma unroll
                        for (int j = 0; j < 4; j++) {
                            float ao = a2s[o0 + j][cc];
                            acc[h][w][0][j] += ai0 * ao;
                            acc[h][w][1][j] += ai1 * ao;
                        }
                    }
                }
            }
        }
    }
#pragma unroll
    for (int h = 0; h < 3; h++)
#pragma unroll
        for (int w = 0; w < 3; w++)
#pragma unroll
            for (int ii = 0; ii < 2; ii++)
#pragma unroll
                for (int j = 0; j < 4; j++) {
                    atomicAdd(&g_attn[((size_t)b*CC_ + ob + o0 + j)*KK
                                      + (size_t)(ib + i0 + ii)*9 + h*3 + w],
                              acc[h][w][ii][j]);
                }
}

// ---------------- softmax over (i,h,w) per (b,o); writes transposed kernels --
__global__ __launch_bounds__(256) void softmax_kernel() {
    __shared__ float red[256];
    const int row = blockIdx.x;               // b*128 + o
    const int b = row >> 7, o = row & 127;
    const float* rp = g_attn + (size_t)row*KK;
    const float scale = 0.029462782549439483f;   // 1/sqrt(1152)
    const int tid = threadIdx.x;

    float m = -1e30f;
    for (int e = tid; e < KK; e += 256) m = fmaxf(m, rp[e]);
    red[tid] = m; __syncthreads();
    for (int s = 128; s > 0; s >>= 1) {
        if (tid < s) red[tid] = fmaxf(red[tid], red[tid + s]);
        __syncthreads();
    }
    m = red[0] * scale;
    __syncthreads();

    float sum = 0.f;
    for (int e = tid; e < KK; e += 256) sum += expf(rp[e]*scale - m);
    red[tid] = sum; __syncthreads();
    for (int s = 128; s > 0; s >>= 1) {
        if (tid < s) red[tid] += red[tid + s];
        __syncthreads();
    }
    float inv = 1.f / red[0];

    for (int e = tid; e < KK; e += 256)
        g_kern[((size_t)b*KK + e)*CC_ + o] = expf(rp[e]*scale - m) * inv;
}

// ---------------- BN stats over av partitioned by (group, parity) ------------
__global__ __launch_bounds__(256) void stats_kernel() {
    const int g = blockIdx.x;   // 0..31
    const int b = blockIdx.y;   // 0..7
    const int tid = threadIdx.x;
    float s00=0,s01=0,s10=0,s11=0,q00=0,q01=0,q10=0,q11=0;
    for (int c = 0; c < 4; c++) {
        const float* p = g_av + ((size_t)b*CC_ + g*4 + c)*HW;
        for (int e = tid; e < HW/2; e += 256) {
            int y = e / 96;
            int x2 = (e - y*96) * 2;
            float v0 = p[y*WW + x2];
            float v1 = p[y*WW + x2 + 1];
            if (y & 1) { s10 += v0; q10 += v0*v0; s11 += v1; q11 += v1*v1; }
            else       { s00 += v0; q00 += v0*v0; s01 += v1; q01 += v1*v1; }
        }
    }
    __shared__ float red[256];
    float vals[8] = {s00, s01, s10, s11, q00, q01, q10, q11};
#pragma unroll
    for (int v = 0; v < 8; v++) {
        red[tid] = vals[v]; __syncthreads();
        for (int st = 128; st > 0; st >>= 1) {
            if (tid < st) red[tid] += red[tid + st];
            __syncthreads();
        }
        if (tid == 0) {
            int p2 = v & 3;
            if (v < 4) atomicAdd(&g_sum[g*4 + p2],   red[0]);
            else       atomicAdd(&g_sumsq[g*4 + p2], red[0]);
        }
        __syncthreads();
    }
}

__global__ void finalize_kernel() {
    int c = threadIdx.x;
    if (c < CC_) {
        float n = (float)STAT_N;
        float mean = g_sum[c] / n;
        float var  = g_sumsq[c] / n - mean*mean;
        g_mean[c] = mean;
        g_inv[c]  = NORM_SCALE * rsqrtf(var + EPSV);
    }
}

// ---------------- fused stack-gather + BN + residual epilogue ----------------
__global__ __launch_bounds__(256) void output_kernel(const float* __restrict__ x,
                                                     const float* __restrict__ mom_p,
                                                     float* __restrict__ out) {
    const float mom = *mom_p;
    for (size_t idx = (size_t)blockIdx.x*blockDim.x + threadIdx.x; idx < (size_t)TOT;
         idx += (size_t)gridDim.x*blockDim.x) {
        size_t b = idx / CHW;
        int r  = (int)(idx - b*CHW);
        int c2 = r / HW;
        int rr = r - c2*HW;
        int Y = rr / WW, X = rr - Y*WW;
        int i2 = (Y >= 96), j2 = (X >= 96);
        int ph = Y - i2*96, pw = X - j2*96;
        int sc = (c2 & ~3) | (i2*2 + j2);
        int sy = ph*2 + ((c2 >> 1) & 1);
        int sx = pw*2 + (c2 & 1);
        float v = g_av[((size_t)b*CC_ + sc)*HW + (size_t)sy*WW + sx];
        out[idx] = mom * x[idx] + (v - g_mean[c2]) * g_inv[c2];
    }
}

// ---------------- launch -----------------------------------------------------
extern "C" void kernel_launch(void* const* d_in, const int* in_sizes, int n_in,
                              void* d_out, int out_size) {
    const float* x   = (const float*)d_in[0];
    const float* w1  = (const float*)d_in[1];
    const float* w2  = (const float*)d_in[2];
    const float* w3  = (const float*)d_in[3];
    const float* mom = (const float*)d_in[4];
    float* out = (float*)d_out;

    float *a1, *a2, *a3, *av, *wt, *kern;
    cudaGetSymbolAddress((void**)&a1,  g_a1);
    cudaGetSymbolAddress((void**)&a2,  g_a2);
    cudaGetSymbolAddress((void**)&a3,  g_a3);
    cudaGetSymbolAddress((void**)&av,  g_av);
    cudaGetSymbolAddress((void**)&wt,  g_wt);
    cudaGetSymbolAddress((void**)&kern, g_kern);

    zero_kernel<<<512, 256>>>();
    wtrans_kernel<<<dim3(72, 3), 256>>>(w1, w2, w3);

    dim3 cgrid((HH/4)*(WW/16), 2, BB);   // (576, 2, 8)
    conv3x3_kernel<<<cgrid, 256>>>(x, wt + 0*(size_t)KK*CC_, a1, 0);
    conv3x3_kernel<<<cgrid, 256>>>(x, wt + 1*(size_t)KK*CC_, a2, 0);
    conv3x3_kernel<<<cgrid, 256>>>(x, wt + 2*(size_t)KK*CC_, a3, 0);

    attn_gemm_kernel<<<dim3(4, 2, 64), 256>>>();
    softmax_kernel<<<BB*CC_, 256>>>();

    conv3x3_kernel<<<cgrid, 256>>>(a3, kern, av, (long)KK*CC_);

    stats_kernel<<<dim3(32, 8), 256>>>();
    finalize_kernel<<<1, 128>>>();
    output_kernel<<<8192, 256>>>(x, mom, out);
}

// round 2
// speedup vs baseline: 1.0005x; 1.0005x over previous
#include <cuda_runtime.h>
#include <cstdint>
#include <cstdio>

#define BB 8
#define CC_ 128
#define HH 192
#define WW 192
#define HW (HH*WW)
#define CHW (CC_*HW)
#define TOT (BB*CHW)
#define KK 1152            // C*9
#define EPSV 1e-5f
#define NORM_SCALE 0.1816f
#define STAT_N (BB*4*(HH/2)*(WW/2))   // 294912

// ---------------- scratch (device globals; no allocations allowed) ------------
__device__ float g_a1[TOT];
__device__ float g_a2[TOT];
__device__ float g_a3[TOT];
__device__ float g_av[TOT];
__device__ float g_wt[3][KK*CC_];     // transposed static weights: [(c*9+k)][o]
__device__ float g_attn[BB*CC_*KK];   // [b][o][i*9+h*3+w]
__device__ float g_kern[(size_t)BB*KK*CC_];   // [b][(i*9+k)][o]
__device__ float g_sum[CC_];
__device__ float g_sumsq[CC_];
__device__ float g_mean[CC_];
__device__ float g_inv[CC_];

// ---------------- packed fp32x2 fma (sm_100+) --------------------------------
__device__ __forceinline__ unsigned long long ffma2(unsigned long long a,
                                                    unsigned long long b,
                                                    unsigned long long c) {
    unsigned long long d;
    asm("fma.rn.f32x2 %0, %1, %2, %3;" : "=l"(d) : "l"(a), "l"(b), "l"(c));
    return d;
}

// ---------------- zero accumulators ------------------------------------------
__global__ void zero_kernel() {
    int n = BB*CC_*KK;
    for (int i = blockIdx.x*blockDim.x + threadIdx.x; i < n; i += gridDim.x*blockDim.x)
        g_attn[i] = 0.f;
    if (blockIdx.x == 0 && threadIdx.x < CC_) {
        g_sum[threadIdx.x] = 0.f;
        g_sumsq[threadIdx.x] = 0.f;
    }
}

// ---------------- transpose static conv weights to [(c*9+k)][o] --------------
__global__ void wtrans_kernel(const float* __restrict__ w1,
                              const float* __restrict__ w2,
                              const float* __restrict__ w3) {
    const float* w = (blockIdx.y == 0) ? w1 : (blockIdx.y == 1) ? w2 : w3;
    for (int e = blockIdx.x*blockDim.x + threadIdx.x; e < KK*CC_; e += gridDim.x*blockDim.x) {
        int r = e / CC_, o = e % CC_;
        g_wt[blockIdx.y][e] = w[(size_t)o*KK + r];
    }
}

// ---------------- direct 3x3 conv (SAME, cross-correlation), fp32x2 ----------
// tile per block: 64 out-channels x (4 rows x 16 cols). 256 threads.
// thread (tx=col, ty -> 4 o's). accumulators are f32x2 pairs along o.
__global__ __launch_bounds__(256) void conv3x3_kernel(const float* __restrict__ in,
                                                      const float* __restrict__ wt,
                                                      float* __restrict__ out,
                                                      long wstride) {
    __shared__ float  Wsm[36][64];       // [ic*9+k][o]  9216 B
    __shared__ float2 Xsm[4][6][18];     // duplicated x  3456 B
    const int b = blockIdx.z;
    const int obase = blockIdx.y * 64;
    const int tiley = blockIdx.x / (WW/16);
    const int tilex = blockIdx.x % (WW/16);
    const int y0 = tiley*4, x0 = tilex*16;
    const float* inb = in + (size_t)b*CHW;
    const float* wtb = wt + (size_t)b*wstride;
    const int tid = threadIdx.x;
    const int tx = tid & 15, ty = tid >> 4;

    unsigned long long acc[2][4];
#pragma unroll
    for (int j = 0; j < 2; j++)
#pragma unroll
        for (int r = 0; r < 4; r++) acc[j][r] = 0ull;

    for (int ic0 = 0; ic0 < CC_; ic0 += 4) {
        __syncthreads();
#pragma unroll
        for (int e = tid; e < 36*64; e += 256) {
            int r = e >> 6, c = e & 63;
            Wsm[r][c] = wtb[(size_t)(ic0*9 + r)*CC_ + obase + c];
        }
        for (int e = tid; e < 432; e += 256) {
            int ic = e / 108; int rem = e - ic*108;
            int r = rem / 18; int cc = rem - r*18;
            int gy = y0 - 1 + r, gx = x0 - 1 + cc;
            float v = 0.f;
            if ((unsigned)gy < HH && (unsigned)gx < WW)
                v = inb[(size_t)(ic0 + ic)*HW + gy*WW + gx];
            Xsm[ic][r][cc] = make_float2(v, v);
        }
        __syncthreads();
#pragma unroll
        for (int ic = 0; ic < 4; ic++) {
#pragma unroll
            for (int ky = 0; ky < 3; ky++) {
#pragma unroll
                for (int kx = 0; kx < 3; kx++) {
                    const float* wp = &Wsm[ic*9 + ky*3 + kx][ty << 2];
                    unsigned long long w01 = *(const unsigned long long*)(wp);
                    unsigned long long w23 = *(const unsigned long long*)(wp + 2);
#pragma unroll
                    for (int r = 0; r < 4; r++) {
                        unsigned long long xv =
                            *(const unsigned long long*)&Xsm[ic][r + ky][tx + kx];
                        acc[0][r] = ffma2(w01, xv, acc[0][r]);
                        acc[1][r] = ffma2(w23, xv, acc[1][r]);
                    }
                }
            }
        }
    }
    float* outb = out + (size_t)b*CHW;
#pragma unroll
    for (int j = 0; j < 2; j++) {
#pragma unroll
        for (int r = 0; r < 4; r++) {
            unsigned long long a = acc[j][r];
            float lo = __uint_as_float((unsigned)a);
            float hi = __uint_as_float((unsigned)(a >> 32));
            int o = obase + (ty << 2) + j*2;
            size_t base = (size_t)o*HW + (size_t)(y0 + r)*WW + x0 + tx;
            outb[base]      = lo;
            outb[base + HW] = hi;
        }
    }
}

// ---------------- attention correlation GEMM ---------------------------------
// attn[b,h,w,i,o] = sum over positions with y%3==h, x%3==w of a1[i,pos]*a2[o,pos]
// block: 32 i x 64 o tile, one batch, one 24-row y-chunk. parity via unrolling.
__global__ __launch_bounds__(256) void attn_gemm_kernel() {
    __shared__ float a1s[96][34];   // [xcol][i]
    __shared__ float a2s[64][97];   // [o][xcol]
    const int ib = blockIdx.x * 32;
    const int ob = blockIdx.y * 64;
    const int b  = blockIdx.z >> 3;
    const int yb = (blockIdx.z & 7) * 24;
    const int tid = threadIdx.x;
    const int o0 = (tid & 15) * 4;
    const int i0 = (tid >> 4) * 2;
    const float* a1b = g_a1 + (size_t)b*CHW;
    const float* a2b = g_a2 + (size_t)b*CHW;

    float acc[3][3][2][4];
#pragma unroll
    for (int h = 0; h < 3; h++)
#pragma unroll
        for (int w = 0; w < 3; w++)
#pragma unroll
            for (int ii = 0; ii < 2; ii++)
#pragma unroll
                for (int j = 0; j < 4; j++) acc[h][w][ii][j] = 0.f;

    for (int y3 = 0; y3 < 8; y3++) {
#pragma unroll
        for (int h = 0; h < 3; h++) {
            const int y = yb + y3*3 + h;
#pragma unroll
            for (int xc = 0; xc < 192; xc += 96) {
                __syncthreads();
                for (int e = tid; e < 32*96; e += 256) {
                    int ii = e / 96, cc = e - ii*96;
                    a1s[cc][ii] = a1b[(size_t)(ib + ii)*HW + y*WW + xc + cc];
                }
                for (int e = tid; e < 64*96; e += 256) {
                    int oo = e / 96, cc = e - oo*96;
                    a2s[oo][cc] = a2b[(size_t)(ob + oo)*HW + y*WW + xc + cc];
                }
                __syncthreads();
#pragma unroll 2
                for (int x3 = 0; x3 < 32; x3++) {
#pragma unroll
                    for (int w = 0; w < 3; w++) {
                        const int cc = x3*3 + w;
                        float ai0 = a1s[cc][i0];
                        float ai1 = a1s[cc][i0 + 1];
#pragma unroll
                        for (int j = 0; j < 4; j++) {
                            float ao = a2s[o0 + j][cc];
                            acc[h][w][0][j] += ai0 * ao;
                            acc[h][w][1][j] += ai1 * ao;
                        }
                    }
                }
            }
        }
    }
#pragma unroll
    for (int h = 0; h < 3; h++)
#pragma unroll
        for (int w = 0; w < 3; w++)
#pragma unroll
            for (int ii = 0; ii < 2; ii++)
#pragma unroll
                for (int j = 0; j < 4; j++) {
                    atomicAdd(&g_attn[((size_t)b*CC_ + ob + o0 + j)*KK
                                      + (size_t)(ib + i0 + ii)*9 + h*3 + w],
                              acc[h][w][ii][j]);
                }
}

// ---------------- softmax over (i,h,w) per (b,o); writes transposed kernels --
__global__ __launch_bounds__(256) void softmax_kernel() {
    __shared__ float red[256];
    const int row = blockIdx.x;               // b*128 + o
    const int b = row >> 7, o = row & 127;
    const float* rp = g_attn + (size_t)row*KK;
    const float scale = 0.029462782549439483f;   // 1/sqrt(1152)
    const int tid = threadIdx.x;

    float m = -1e30f;
    for (int e = tid; e < KK; e += 256) m = fmaxf(m, rp[e]);
    red[tid] = m; __syncthreads();
    for (int s = 128; s > 0; s >>= 1) {
        if (tid < s) red[tid] = fmaxf(red[tid], red[tid + s]);
        __syncthreads();
    }
    m = red[0] * scale;
    __syncthreads();

    float sum = 0.f;
    for (int e = tid; e < KK; e += 256) sum += expf(rp[e]*scale - m);
    red[tid] = sum; __syncthreads();
    for (int s = 128; s > 0; s >>= 1) {
        if (tid < s) red[tid] += red[tid + s];
        __syncthreads();
    }
    float inv = 1.f / red[0];

    for (int e = tid; e < KK; e += 256)
        g_kern[((size_t)b*KK + e)*CC_ + o] = expf(rp[e]*scale - m) * inv;
}

// ---------------- BN stats over av partitioned by (group, parity) ------------
__global__ __launch_bounds__(256) void stats_kernel() {
    const int g = blockIdx.x;   // 0..31
    const int b = blockIdx.y;   // 0..7
    const int tid = threadIdx.x;
    float s00=0,s01=0,s10=0,s11=0,q00=0,q01=0,q10=0,q11=0;
    for (int c = 0; c < 4; c++) {
        const float* p = g_av + ((size_t)b*CC_ + g*4 + c)*HW;
        for (int e = tid; e < HW/2; e += 256) {
            int y = e / 96;
            int x2 = (e - y*96) * 2;
            float v0 = p[y*WW + x2];
            float v1 = p[y*WW + x2 + 1];
            if (y & 1) { s10 += v0; q10 += v0*v0; s11 += v1; q11 += v1*v1; }
            else       { s00 += v0; q00 += v0*v0; s01 += v1; q01 += v1*v1; }
        }
    }
    __shared__ float red[256];
    float vals[8] = {s00, s01, s10, s11, q00, q01, q10, q11};
#pragma unroll
    for (int v = 0; v < 8; v++) {
        red[tid] = vals[v]; __syncthreads();
        for (int st = 128; st > 0; st >>= 1) {
            if (tid < st) red[tid] += red[tid + st];
            __syncthreads();
        }
        if (tid == 0) {
            int p2 = v & 3;
            if (v < 4) atomicAdd(&g_sum[g*4 + p2],   red[0]);
            else       atomicAdd(&g_sumsq[g*4 + p2], red[0]);
        }
        __syncthreads();
    }
}

__global__ void finalize_kernel() {
    int c = threadIdx.x;
    if (c < CC_) {
        float n = (float)STAT_N;
        float mean = g_sum[c] / n;
        float var  = g_sumsq[c] / n - mean*mean;
        g_mean[c] = mean;
        g_inv[c]  = NORM_SCALE * rsqrtf(var + EPSV);
    }
}

// ---------------- fused stack-gather + BN + residual epilogue ----------------
__global__ __launch_bounds__(256) void output_kernel(const float* __restrict__ x,
                                                     const float* __restrict__ mom_p,
                                                     float* __restrict__ out) {
    const float mom = *mom_p;
    for (size_t idx = (size_t)blockIdx.x*blockDim.x + threadIdx.x; idx < (size_t)TOT;
         idx += (size_t)gridDim.x*blockDim.x) {
        size_t b = idx / CHW;
        int r  = (int)(idx - b*CHW);
        int c2 = r / HW;
        int rr = r - c2*HW;
        int Y = rr / WW, X = rr - Y*WW;
        int i2 = (Y >= 96), j2 = (X >= 96);
        int ph = Y - i2*96, pw = X - j2*96;
        int sc = (c2 & ~3) | (i2*2 + j2);
        int sy = ph*2 + ((c2 >> 1) & 1);
        int sx = pw*2 + (c2 & 1);
        float v = g_av[((size_t)b*CC_ + sc)*HW + (size_t)sy*WW + sx];
        out[idx] = mom * x[idx] + (v - g_mean[c2]) * g_inv[c2];
    }
}

// ---------------- launch -----------------------------------------------------
extern "C" void kernel_launch(void* const* d_in, const int* in_sizes, int n_in,
                              void* d_out, int out_size) {
    const float* x   = (const float*)d_in[0];
    const float* w1  = (const float*)d_in[1];
    const float* w2  = (const float*)d_in[2];
    const float* w3  = (const float*)d_in[3];
    const float* mom = (const float*)d_in[4];
    float* out = (float*)d_out;

    float *a1, *a2, *a3, *av, *wt, *kern;
    cudaGetSymbolAddress((void**)&a1,  g_a1);
    cudaGetSymbolAddress((void**)&a2,  g_a2);
    cudaGetSymbolAddress((void**)&a3,  g_a3);
    cudaGetSymbolAddress((void**)&av,  g_av);
    cudaGetSymbolAddress((void**)&wt,  g_wt);
    cudaGetSymbolAddress((void**)&kern, g_kern);

    zero_kernel<<<512, 256>>>();
    wtrans_kernel<<<dim3(72, 3), 256>>>(w1, w2, w3);

    dim3 cgrid((HH/4)*(WW/16), 2, BB);   // (576, 2, 8)
    conv3x3_kernel<<<cgrid, 256>>>(x, wt + 0*(size_t)KK*CC_, a1, 0);
    conv3x3_kernel<<<cgrid, 256>>>(x, wt + 1*(size_t)KK*CC_, a2, 0);
    conv3x3_kernel<<<cgrid, 256>>>(x, wt + 2*(size_t)KK*CC_, a3, 0);

    attn_gemm_kernel<<<dim3(4, 2, 64), 256>>>();
    softmax_kernel<<<BB*CC_, 256>>>();

    conv3x3_kernel<<<cgrid, 256>>>(a3, kern, av, (long)KK*CC_);

    stats_kernel<<<dim3(32, 8), 256>>>();
    finalize_kernel<<<1, 128>>>();
    output_kernel<<<8192, 256>>>(x, mom, out);
}

// round 3
// speedup vs baseline: 1.1054x; 1.1048x over previous
#include <cuda_runtime.h>
#include <cstdint>
#include <cstdio>

#define BB 8
#define CC_ 128
#define HH 192
#define WW 192
#define HW (HH*WW)
#define CHW (CC_*HW)
#define TOT (BB*CHW)
#define KK 1152            // C*9
#define EPSV 1e-5f
#define NORM_SCALE 0.1816f
#define STAT_N (BB*4*(HH/2)*(WW/2))   // 294912

// ---------------- scratch (device globals; no allocations allowed) ------------
__device__ float g_a1[TOT];
__device__ float g_a2[TOT];
__device__ float g_a3[TOT];
__device__ float g_av[TOT];
__device__ float g_wt[3][KK*CC_];     // transposed static weights: [(c*9+k)][o]
__device__ float g_attn[BB*CC_*KK];   // [b][o][i*9+h*3+w]
__device__ float g_kern[(size_t)BB*KK*CC_];   // [b][(i*9+k)][o]
__device__ float g_sum[CC_];
__device__ float g_sumsq[CC_];
__device__ float g_mean[CC_];
__device__ float g_inv[CC_];

// ---------------- packed fp32x2 fma (sm_100+) --------------------------------
__device__ __forceinline__ unsigned long long ffma2(unsigned long long a,
                                                    unsigned long long b,
                                                    unsigned long long c) {
    unsigned long long d;
    asm("fma.rn.f32x2 %0, %1, %2, %3;" : "=l"(d) : "l"(a), "l"(b), "l"(c));
    return d;
}

// ---------------- zero accumulators ------------------------------------------
__global__ void zero_kernel() {
    int n = BB*CC_*KK;
    for (int i = blockIdx.x*blockDim.x + threadIdx.x; i < n; i += gridDim.x*blockDim.x)
        g_attn[i] = 0.f;
    if (blockIdx.x == 0 && threadIdx.x < CC_) {
        g_sum[threadIdx.x] = 0.f;
        g_sumsq[threadIdx.x] = 0.f;
    }
}

// ---------------- transpose static conv weights to [(c*9+k)][o] --------------
__global__ void wtrans_kernel(const float* __restrict__ w1,
                              const float* __restrict__ w2,
                              const float* __restrict__ w3) {
    const float* w = (blockIdx.y == 0) ? w1 : (blockIdx.y == 1) ? w2 : w3;
    for (int e = blockIdx.x*blockDim.x + threadIdx.x; e < KK*CC_; e += gridDim.x*blockDim.x) {
        int r = e / CC_, o = e % CC_;
        g_wt[blockIdx.y][e] = w[(size_t)o*KK + r];
    }
}

// ---------------- direct 3x3 conv (SAME, cross-correlation), fp32x2 ----------
// tile per block: all 128 out-channels x (4 rows x 16 cols). 256 threads.
// thread (tx=col, ty -> 8 o's). x halo staged in registers per ic; weights
// loaded as 4 LDS.64 per k, each serving 16 FFMA2.
__global__ __launch_bounds__(256, 2) void conv3x3_kernel(const float* __restrict__ in,
                                                         const float* __restrict__ wt,
                                                         float* __restrict__ out,
                                                         long wstride) {
    __shared__ float  Wsm[36][128];      // [ic*9+k][o]  18432 B
    __shared__ float2 Xsm[4][6][18];     // duplicated x  3456 B
    const int b = blockIdx.z;
    const int tiley = blockIdx.x / (WW/16);
    const int tilex = blockIdx.x % (WW/16);
    const int y0 = tiley*4, x0 = tilex*16;
    const float* inb = in + (size_t)b*CHW;
    const float* wtb = wt + (size_t)b*wstride;
    const int tid = threadIdx.x;
    const int tx = tid & 15, ty = tid >> 4;

    unsigned long long acc[4][4];        // [o-pair][row]
#pragma unroll
    for (int j = 0; j < 4; j++)
#pragma unroll
        for (int r = 0; r < 4; r++) acc[j][r] = 0ull;

    for (int ic0 = 0; ic0 < CC_; ic0 += 4) {
        __syncthreads();
#pragma unroll
        for (int e = tid; e < 36*128; e += 256) {
            int r = e >> 7, c = e & 127;
            Wsm[r][c] = wtb[(size_t)(ic0*9 + r)*CC_ + c];
        }
#pragma unroll
        for (int e = tid; e < 432; e += 256) {
            int ic = e / 108; int rem = e - ic*108;
            int r = rem / 18; int cc = rem - r*18;
            int gy = y0 - 1 + r, gx = x0 - 1 + cc;
            float v = 0.f;
            if ((unsigned)gy < HH && (unsigned)gx < WW)
                v = inb[(size_t)(ic0 + ic)*HW + gy*WW + gx];
            Xsm[ic][r][cc] = make_float2(v, v);
        }
        __syncthreads();
#pragma unroll
        for (int ic = 0; ic < 4; ic++) {
            // stage the 6-row x 3-col x window for this ic in registers
            unsigned long long xr[6][3];
#pragma unroll
            for (int ir = 0; ir < 6; ir++)
#pragma unroll
                for (int c = 0; c < 3; c++)
                    xr[ir][c] = *(const unsigned long long*)&Xsm[ic][ir][tx + c];
#pragma unroll
            for (int ky = 0; ky < 3; ky++) {
#pragma unroll
                for (int kx = 0; kx < 3; kx++) {
                    const float* wp = &Wsm[ic*9 + ky*3 + kx][ty << 3];
                    unsigned long long w0 = *(const unsigned long long*)(wp);
                    unsigned long long w1 = *(const unsigned long long*)(wp + 2);
                    unsigned long long w2 = *(const unsigned long long*)(wp + 4);
                    unsigned long long w3 = *(const unsigned long long*)(wp + 6);
#pragma unroll
                    for (int r = 0; r < 4; r++) {
                        unsigned long long xv = xr[r + ky][kx];
                        acc[0][r] = ffma2(w0, xv, acc[0][r]);
                        acc[1][r] = ffma2(w1, xv, acc[1][r]);
                        acc[2][r] = ffma2(w2, xv, acc[2][r]);
                        acc[3][r] = ffma2(w3, xv, acc[3][r]);
                    }
                }
            }
        }
    }
    float* outb = out + (size_t)b*CHW;
#pragma unroll
    for (int j = 0; j < 4; j++) {
#pragma unroll
        for (int r = 0; r < 4; r++) {
            unsigned long long a = acc[j][r];
            float lo = __uint_as_float((unsigned)a);
            float hi = __uint_as_float((unsigned)(a >> 32));
            int o = (ty << 3) + j*2;
            size_t base = (size_t)o*HW + (size_t)(y0 + r)*WW + x0 + tx;
            outb[base]      = lo;
            outb[base + HW] = hi;
        }
    }
}

// ---------------- attention correlation GEMM ---------------------------------
// attn[b,h,w,i,o] = sum over positions with y%3==h, x%3==w of a1[i,pos]*a2[o,pos]
// block: 32 i x 64 o tile, one batch, one 24-row y-chunk. parity via unrolling.
__global__ __launch_bounds__(256) void attn_gemm_kernel() {
    __shared__ float a1s[96][34];   // [xcol][i]
    __shared__ float a2s[64][97];   // [o][xcol]
    const int ib = blockIdx.x * 32;
    const int ob = blockIdx.y * 64;
    const int b  = blockIdx.z >> 3;
    const int yb = (blockIdx.z & 7) * 24;
    const int tid = threadIdx.x;
    const int o0 = (tid & 15) * 4;
    const int i0 = (tid >> 4) * 2;
    const float* a1b = g_a1 + (size_t)b*CHW;
    const float* a2b = g_a2 + (size_t)b*CHW;

    float acc[3][3][2][4];
#pragma unroll
    for (int h = 0; h < 3; h++)
#pragma unroll
        for (int w = 0; w < 3; w++)
#pragma unroll
            for (int ii = 0; ii < 2; ii++)
#pragma unroll
                for (int j = 0; j < 4; j++) acc[h][w][ii][j] = 0.f;

    for (int y3 = 0; y3 < 8; y3++) {
#pragma unroll
        for (int h = 0; h < 3; h++) {
            const int y = yb + y3*3 + h;
#pragma unroll
            for (int xc = 0; xc < 192; xc += 96) {
                __syncthreads();
                for (int e = tid; e < 32*96; e += 256) {
                    int ii = e / 96, cc = e - ii*96;
                    a1s[cc][ii] = a1b[(size_t)(ib + ii)*HW + y*WW + xc + cc];
                }
                for (int e = tid; e < 64*96; e += 256) {
                    int oo = e / 96, cc = e - oo*96;
                    a2s[oo][cc] = a2b[(size_t)(ob + oo)*HW + y*WW + xc + cc];
                }
                __syncthreads();
#pragma unroll 2
                for (int x3 = 0; x3 < 32; x3++) {
#pragma unroll
                    for (int w = 0; w < 3; w++) {
                        const int cc = x3*3 + w;
                        float ai0 = a1s[cc][i0];
                        float ai1 = a1s[cc][i0 + 1];
#pragma unroll
                        for (int j = 0; j < 4; j++) {
                            float ao = a2s[o0 + j][cc];
                            acc[h][w][0][j] += ai0 * ao;
                            acc[h][w][1][j] += ai1 * ao;
                        }
                    }
                }
            }
        }
    }
#pragma unroll
    for (int h = 0; h < 3; h++)
#pragma unroll
        for (int w = 0; w < 3; w++)
#pragma unroll
            for (int ii = 0; ii < 2; ii++)
#pragma unroll
                for (int j = 0; j < 4; j++) {
                    atomicAdd(&g_attn[((size_t)b*CC_ + ob + o0 + j)*KK
                                      + (size_t)(ib + i0 + ii)*9 + h*3 + w],
                              acc[h][w][ii][j]);
                }
}

// ---------------- softmax over (i,h,w) per (b,o); writes transposed kernels --
__global__ __launch_bounds__(256) void softmax_kernel() {
    __shared__ float red[256];
    const int row = blockIdx.x;               // b*128 + o
    const int b = row >> 7, o = row & 127;
    const float* rp = g_attn + (size_t)row*KK;
    const float scale = 0.029462782549439483f;   // 1/sqrt(1152)
    const int tid = threadIdx.x;

    float m = -1e30f;
    for (int e = tid; e < KK; e += 256) m = fmaxf(m, rp[e]);
    red[tid] = m; __syncthreads();
    for (int s = 128; s > 0; s >>= 1) {
        if (tid < s) red[tid] = fmaxf(red[tid], red[tid + s]);
        __syncthreads();
    }
    m = red[0] * scale;
    __syncthreads();

    float sum = 0.f;
    for (int e = tid; e < KK; e += 256) sum += expf(rp[e]*scale - m);
    red[tid] = sum; __syncthreads();
    for (int s = 128; s > 0; s >>= 1) {
        if (tid < s) red[tid] += red[tid + s];
        __syncthreads();
    }
    float inv = 1.f / red[0];

    for (int e = tid; e < KK; e += 256)
        g_kern[((size_t)b*KK + e)*CC_ + o] = expf(rp[e]*scale - m) * inv;
}

// ---------------- BN stats over av partitioned by (group, parity) ------------
__global__ __launch_bounds__(256) void stats_kernel() {
    const int g = blockIdx.x;   // 0..31
    const int b = blockIdx.y;   // 0..7
    const int tid = threadIdx.x;
    float s00=0,s01=0,s10=0,s11=0,q00=0,q01=0,q10=0,q11=0;
    for (int c = 0; c < 4; c++) {
        const float* p = g_av + ((size_t)b*CC_ + g*4 + c)*HW;
        for (int e = tid; e < HW/2; e += 256) {
            int y = e / 96;
            int x2 = (e - y*96) * 2;
            float v0 = p[y*WW + x2];
            float v1 = p[y*WW + x2 + 1];
            if (y & 1) { s10 += v0; q10 += v0*v0; s11 += v1; q11 += v1*v1; }
            else       { s00 += v0; q00 += v0*v0; s01 += v1; q01 += v1*v1; }
        }
    }
    __shared__ float red[256];
    float vals[8] = {s00, s01, s10, s11, q00, q01, q10, q11};
#pragma unroll
    for (int v = 0; v < 8; v++) {
        red[tid] = vals[v]; __syncthreads();
        for (int st = 128; st > 0; st >>= 1) {
            if (tid < st) red[tid] += red[tid + st];
            __syncthreads();
        }
        if (tid == 0) {
            int p2 = v & 3;
            if (v < 4) atomicAdd(&g_sum[g*4 + p2],   red[0]);
            else       atomicAdd(&g_sumsq[g*4 + p2], red[0]);
        }
        __syncthreads();
    }
}

__global__ void finalize_kernel() {
    int c = threadIdx.x;
    if (c < CC_) {
        float n = (float)STAT_N;
        float mean = g_sum[c] / n;
        float var  = g_sumsq[c] / n - mean*mean;
        g_mean[c] = mean;
        g_inv[c]  = NORM_SCALE * rsqrtf(var + EPSV);
    }
}

// ---------------- fused stack-gather + BN + residual epilogue ----------------
__global__ __launch_bounds__(256) void output_kernel(const float* __restrict__ x,
                                                     const float* __restrict__ mom_p,
                                                     float* __restrict__ out) {
    const float mom = *mom_p;
    for (size_t idx = (size_t)blockIdx.x*blockDim.x + threadIdx.x; idx < (size_t)TOT;
         idx += (size_t)gridDim.x*blockDim.x) {
        size_t b = idx / CHW;
        int r  = (int)(idx - b*CHW);
        int c2 = r / HW;
        int rr = r - c2*HW;
        int Y = rr / WW, X = rr - Y*WW;
        int i2 = (Y >= 96), j2 = (X >= 96);
        int ph = Y - i2*96, pw = X - j2*96;
        int sc = (c2 & ~3) | (i2*2 + j2);
        int sy = ph*2 + ((c2 >> 1) & 1);
        int sx = pw*2 + (c2 & 1);
        float v = g_av[((size_t)b*CC_ + sc)*HW + (size_t)sy*WW + sx];
        out[idx] = mom * x[idx] + (v - g_mean[c2]) * g_inv[c2];
    }
}

// ---------------- launch -----------------------------------------------------
extern "C" void kernel_launch(void* const* d_in, const int* in_sizes, int n_in,
                              void* d_out, int out_size) {
    const float* x   = (const float*)d_in[0];
    const float* w1  = (const float*)d_in[1];
    const float* w2  = (const float*)d_in[2];
    const float* w3  = (const float*)d_in[3];
    const float* mom = (const float*)d_in[4];
    float* out = (float*)d_out;

    float *a1, *a2, *a3, *av, *wt, *kern;
    cudaGetSymbolAddress((void**)&a1,  g_a1);
    cudaGetSymbolAddress((void**)&a2,  g_a2);
    cudaGetSymbolAddress((void**)&a3,  g_a3);
    cudaGetSymbolAddress((void**)&av,  g_av);
    cudaGetSymbolAddress((void**)&wt,  g_wt);
    cudaGetSymbolAddress((void**)&kern, g_kern);

    zero_kernel<<<512, 256>>>();
    wtrans_kernel<<<dim3(72, 3), 256>>>(w1, w2, w3);

    dim3 cgrid((HH/4)*(WW/16), 1, BB);   // (576, 1, 8)
    conv3x3_kernel<<<cgrid, 256>>>(x, wt + 0*(size_t)KK*CC_, a1, 0);
    conv3x3_kernel<<<cgrid, 256>>>(x, wt + 1*(size_t)KK*CC_, a2, 0);
    conv3x3_kernel<<<cgrid, 256>>>(x, wt + 2*(size_t)KK*CC_, a3, 0);

    attn_gemm_kernel<<<dim3(4, 2, 64), 256>>>();
    softmax_kernel<<<BB*CC_, 256>>>();

    conv3x3_kernel<<<cgrid, 256>>>(a3, kern, av, (long)KK*CC_);

    stats_kernel<<<dim3(32, 8), 256>>>();
    finalize_kernel<<<1, 128>>>();
    output_kernel<<<8192, 256>>>(x, mom, out);
}

// round 5
// speedup vs baseline: 1.4624x; 1.3230x over previous
#include <cuda_runtime.h>
#include <cuda_bf16.h>
#include <cstdint>
#include <cstdio>

#define BB 8
#define CC_ 128
#define HH 192
#define WW 192
#define HW (HH*WW)
#define CHW (CC_*HW)
#define TOT (BB*CHW)
#define KK 1152            // C*9
#define EPSV 1e-5f
#define NORM_SCALE 0.1816f
#define STAT_N (BB*4*(HH/2)*(WW/2))   // 294912

// ---------------- scratch (device globals; no allocations allowed) ------------
__device__ __align__(16) __nv_bfloat16 g_xh[TOT];
__device__ __align__(16) __nv_bfloat16 g_xl[TOT];
__device__ float g_a1[TOT];
__device__ float g_a2[TOT];
__device__ __align__(16) __nv_bfloat16 g_a3h[TOT];
__device__ __align__(16) __nv_bfloat16 g_a3l[TOT];
__device__ float g_av[TOT];
__device__ __align__(16) __nv_bfloat16 g_wh[3*CC_*KK];    // static weights, [w][o][k]
__device__ __align__(16) __nv_bfloat16 g_wl[3*CC_*KK];
__device__ __align__(16) __nv_bfloat16 g_kh[BB*CC_*KK];   // dynamic kernels, [b][o][k]
__device__ __align__(16) __nv_bfloat16 g_kl[BB*CC_*KK];
__device__ float g_attn[BB*CC_*KK];        // [b][o][i*9+h*3+w]
__device__ float g_sum[CC_];
__device__ float g_sumsq[CC_];
__device__ float g_mean[CC_];
__device__ float g_inv[CC_];

// ---------------- PTX helpers -------------------------------------------------
__device__ __forceinline__ uint32_t smem_u32(const void* p) {
    uint32_t a;
    asm("{ .reg .u64 t; cvta.to.shared.u64 t, %1; cvt.u32.u64 %0, t; }"
        : "=r"(a) : "l"(p));
    return a;
}

__device__ __forceinline__ void ldsm4(unsigned* r, uint32_t addr) {
    asm volatile("ldmatrix.sync.aligned.m8n8.x4.shared.b16 {%0,%1,%2,%3}, [%4];"
                 : "=r"(r[0]), "=r"(r[1]), "=r"(r[2]), "=r"(r[3]) : "r"(addr));
}
__device__ __forceinline__ void ldsm4t(unsigned* r, uint32_t addr) {
    asm volatile("ldmatrix.sync.aligned.m8n8.x4.trans.shared.b16 {%0,%1,%2,%3}, [%4];"
                 : "=r"(r[0]), "=r"(r[1]), "=r"(r[2]), "=r"(r[3]) : "r"(addr));
}
__device__ __forceinline__ void mma_bf16(float* d, const unsigned* a, const unsigned* b) {
    asm volatile(
        "mma.sync.aligned.m16n8k16.row.col.f32.bf16.bf16.f32 "
        "{%0,%1,%2,%3}, {%4,%5,%6,%7}, {%8,%9}, {%0,%1,%2,%3};"
        : "+f"(d[0]), "+f"(d[1]), "+f"(d[2]), "+f"(d[3])
        : "r"(a[0]), "r"(a[1]), "r"(a[2]), "r"(a[3]), "r"(b[0]), "r"(b[1]));
}

// ---------------- zero accumulators ------------------------------------------
__global__ void zero_kernel() {
    int n = BB*CC_*KK;
    for (int i = blockIdx.x*blockDim.x + threadIdx.x; i < n; i += gridDim.x*blockDim.x)
        g_attn[i] = 0.f;
    if (blockIdx.x == 0 && threadIdx.x < CC_) {
        g_sum[threadIdx.x] = 0.f;
        g_sumsq[threadIdx.x] = 0.f;
    }
}

// ---------------- split input x into bf16 hi/lo -------------------------------
__global__ void split_x_kernel(const float* __restrict__ x) {
    for (size_t i = (size_t)blockIdx.x*blockDim.x + threadIdx.x; i < (size_t)TOT;
         i += (size_t)gridDim.x*blockDim.x) {
        float v = x[i];
        __nv_bfloat16 h = __float2bfloat16(v);
        g_xh[i] = h;
        g_xl[i] = __float2bfloat16(v - __bfloat162float(h));
    }
}

// ---------------- split static weights into bf16 hi/lo (natural [o][k]) ------
__global__ void split_w_kernel(const float* __restrict__ w1,
                               const float* __restrict__ w2,
                               const float* __restrict__ w3) {
    const float* w = (blockIdx.y == 0) ? w1 : (blockIdx.y == 1) ? w2 : w3;
    int base = blockIdx.y * CC_ * KK;
    for (int e = blockIdx.x*blockDim.x + threadIdx.x; e < CC_*KK;
         e += gridDim.x*blockDim.x) {
        float v = w[e];
        __nv_bfloat16 h = __float2bfloat16(v);
        g_wh[base + e] = h;
        g_wl[base + e] = __float2bfloat16(v - __bfloat162float(h));
    }
}

// ---------------- bf16 tensor-core implicit-GEMM 3x3 conv ---------------------
// CTA: M=128 out-channels x N=96 pixels (half image row), K=1152 in 36 chunks
// of 32. 8 warps = 4(m) x 2(n); warp tile m32 x n48. 3-product bf16 split.
#define A_STRIDE 80     // 32 bf16 = 64B + 16B pad
#define B_STRIDE 208    // 96 bf16 = 192B + 16B pad

__global__ __launch_bounds__(256, 2) void conv_mma_kernel(
    const __nv_bfloat16* __restrict__ inh, const __nv_bfloat16* __restrict__ inl,
    const __nv_bfloat16* __restrict__ wh_g, const __nv_bfloat16* __restrict__ wl_g,
    long wbstride, float* __restrict__ out1,
    __nv_bfloat16* __restrict__ oh, __nv_bfloat16* __restrict__ ol, int split_out)
{
    __shared__ __align__(16) unsigned char Asm[2][128*A_STRIDE];   // hi, lo
    __shared__ __align__(16) unsigned char Bsm[2][32*B_STRIDE];    // hi, lo
    const int b  = blockIdx.z;
    const int y  = blockIdx.y;
    const int x0 = blockIdx.x * 96;
    const int tid = threadIdx.x;
    const int lane = tid & 31, wid = tid >> 5;
    const int wm = wid & 3, wn = wid >> 2;

    const __nv_bfloat16* wh = wh_g + (size_t)b*wbstride;
    const __nv_bfloat16* wl = wl_g + (size_t)b*wbstride;
    const __nv_bfloat16* inhb = inh + (size_t)b*CHW;
    const __nv_bfloat16* inlb = inl + (size_t)b*CHW;

    float acc[2][6][4];
#pragma unroll
    for (int mh = 0; mh < 2; mh++)
#pragma unroll
        for (int j = 0; j < 6; j++)
#pragma unroll
            for (int t = 0; t < 4; t++) acc[mh][j][t] = 0.f;

    const uint32_t Ah_s = smem_u32(Asm[0]);
    const uint32_t Al_s = smem_u32(Asm[1]);
    const uint32_t Bh_s = smem_u32(Bsm[0]);
    const uint32_t Bl_s = smem_u32(Bsm[1]);

    for (int c = 0; c < 36; c++) {
        __syncthreads();
        // ---- A: weights [o][k0..k0+31] hi/lo, 16B copies
#pragma unroll
        for (int i = 0; i < 4; i++) {
            int slot = tid + i*256;             // < 1024
            int hl = slot >> 9, rem = slot & 511;
            int o = rem >> 2, q = rem & 3;
            const uint4* src = (const uint4*)((hl ? wl : wh) + (size_t)o*KK + c*32) + q;
            *(uint4*)(&Asm[hl][o*A_STRIDE + q*16]) = *src;
        }
        // ---- B: im2col [k][n] hi/lo, bf16x2 stores
#pragma unroll
        for (int i = 0; i < 12; i++) {
            int slot = tid + i*256;             // < 3072
            int rowt = slot / 48, np = slot - rowt*48;
            int k = rowt & 31, hl = rowt >> 5;
            int kg = c*32 + k;
            int ic = kg / 9, rem = kg - ic*9;
            int r = rem / 3, dx = rem - r*3;
            int gy = y + r - 1;
            int gx = x0 + np*2 + dx - 1;
            __nv_bfloat162 pk;
            pk.x = __float2bfloat16(0.f); pk.y = pk.x;
            if ((unsigned)gy < HH) {
                const __nv_bfloat16* src = (hl ? inlb : inhb) + (size_t)ic*HW + gy*WW;
                if ((unsigned)gx < WW)     pk.x = src[gx];
                if ((unsigned)(gx+1) < WW) pk.y = src[gx+1];
            }
            *(__nv_bfloat162*)(&Bsm[hl][k*B_STRIDE + np*4]) = pk;
        }
        __syncthreads();

#pragma unroll
        for (int s = 0; s < 2; s++) {
            unsigned Ah[2][4], Al[2][4], Bh[3][4], Bl[3][4];
#pragma unroll
            for (int mh = 0; mh < 2; mh++) {
                uint32_t off = (uint32_t)(wm*32 + mh*16 + (lane & 15))*A_STRIDE
                             + ((lane >> 4) << 4) + s*32;
                ldsm4(Ah[mh], Ah_s + off);
                ldsm4(Al[mh], Al_s + off);
            }
#pragma unroll
            for (int nf = 0; nf < 3; nf++) {
                uint32_t off = (uint32_t)(s*16 + (lane & 15))*B_STRIDE
                             + wn*96 + nf*32 + ((lane >> 4) << 4);
                ldsm4t(Bh[nf], Bh_s + off);
                ldsm4t(Bl[nf], Bl_s + off);
            }
#pragma unroll
            for (int mh = 0; mh < 2; mh++) {
#pragma unroll
                for (int j = 0; j < 6; j++) {
                    const unsigned* bh = &Bh[j >> 1][(j & 1)*2];
                    const unsigned* bl = &Bl[j >> 1][(j & 1)*2];
                    mma_bf16(acc[mh][j], Ah[mh], bh);
                    mma_bf16(acc[mh][j], Ah[mh], bl);
                    mma_bf16(acc[mh][j], Al[mh], bh);
                }
            }
        }
    }

    // ---- epilogue
#pragma unroll
    for (int mh = 0; mh < 2; mh++) {
        int o = wm*32 + mh*16 + (lane >> 2);
#pragma unroll
        for (int j = 0; j < 6; j++) {
            int x = x0 + wn*48 + j*8 + (lane & 3)*2;
            size_t i0 = ((size_t)b*CC_ + o)*HW + (size_t)y*WW + x;
            size_t i1 = i0 + (size_t)8*HW;
            if (!split_out) {
                *(float2*)(out1 + i0) = make_float2(acc[mh][j][0], acc[mh][j][1]);
                *(float2*)(out1 + i1) = make_float2(acc[mh][j][2], acc[mh][j][3]);
            } else {
                float v0 = acc[mh][j][0], v1 = acc[mh][j][1];
                float v2 = acc[mh][j][2], v3 = acc[mh][j][3];
                __nv_bfloat16 h0 = __float2bfloat16(v0), h1 = __float2bfloat16(v1);
                __nv_bfloat16 h2 = __float2bfloat16(v2), h3 = __float2bfloat16(v3);
                __nv_bfloat162 ph0; ph0.x = h0; ph0.y = h1;
                __nv_bfloat162 ph1; ph1.x = h2; ph1.y = h3;
                __nv_bfloat162 pl0;
                pl0.x = __float2bfloat16(v0 - __bfloat162float(h0));
                pl0.y = __float2bfloat16(v1 - __bfloat162float(h1));
                __nv_bfloat162 pl1;
                pl1.x = __float2bfloat16(v2 - __bfloat162float(h2));
                pl1.y = __float2bfloat16(v3 - __bfloat162float(h3));
                *(__nv_bfloat162*)(oh + i0) = ph0;
                *(__nv_bfloat162*)(oh + i1) = ph1;
                *(__nv_bfloat162*)(ol + i0) = pl0;
                *(__nv_bfloat162*)(ol + i1) = pl1;
            }
        }
    }
}

// ---------------- attention correlation GEMM (fp32 FFMA) ---------------------
__global__ __launch_bounds__(256) void attn_gemm_kernel() {
    __shared__ float a1s[96][34];
    __shared__ float a2s[64][97];
    const int ib = blockIdx.x * 32;
    const int ob = blockIdx.y * 64;
    const int b  = blockIdx.z >> 3;
    const int yb = (blockIdx.z & 7) * 24;
    const int tid = threadIdx.x;
    const int o0 = (tid & 15) * 4;
    const int i0 = (tid >> 4) * 2;
    const float* a1b = g_a1 + (size_t)b*CHW;
    const float* a2b = g_a2 + (size_t)b*CHW;

    float acc[3][3][2][4];
#pragma unroll
    for (int h = 0; h < 3; h++)
#pragma unroll
        for (int w = 0; w < 3; w++)
#pragma unroll
            for (int ii = 0; ii < 2; ii++)
#pragma unroll
                for (int j = 0; j < 4; j++) acc[h][w][ii][j] = 0.f;

    for (int y3 = 0; y3 < 8; y3++) {
#pragma unroll
        for (int h = 0; h < 3; h++) {
            const int y = yb + y3*3 + h;
#pragma unroll
            for (int xc = 0; xc < 192; xc += 96) {
                __syncthreads();
                for (int e = tid; e < 32*96; e += 256) {
                    int ii = e / 96, cc = e - ii*96;
                    a1s[cc][ii] = a1b[(size_t)(ib + ii)*HW + y*WW + xc + cc];
                }
                for (int e = tid; e < 64*96; e += 256) {
                    int oo = e / 96, cc = e - oo*96;
                    a2s[oo][cc] = a2b[(size_t)(ob + oo)*HW + y*WW + xc + cc];
                }
                __syncthreads();
#pragma unroll 2
                for (int x3 = 0; x3 < 32; x3++) {
#pragma unroll
                    for (int w = 0; w < 3; w++) {
                        const int cc = x3*3 + w;
                        float ai0 = a1s[cc][i0];
                        float ai1 = a1s[cc][i0 + 1];
#pragma unroll
                        for (int j = 0; j < 4; j++) {
                            float ao = a2s[o0 + j][cc];
                            acc[h][w][0][j] += ai0 * ao;
                            acc[h][w][1][j] += ai1 * ao;
                        }
                    }
                }
            }
        }
    }
#pragma unroll
    for (int h = 0; h < 3; h++)
#pragma unroll
        for (int w = 0; w < 3; w++)
#pragma unroll
            for (int ii = 0; ii < 2; ii++)
#pragma unroll
                for (int j = 0; j < 4; j++) {
                    atomicAdd(&g_attn[((size_t)b*CC_ + ob + o0 + j)*KK
                                      + (size_t)(ib + i0 + ii)*9 + h*3 + w],
                              acc[h][w][ii][j]);
                }
}

// ---------------- softmax; emits dynamic kernels as bf16 hi/lo [b][o][k] -----
__global__ __launch_bounds__(256) void softmax_kernel() {
    __shared__ float red[256];
    const int row = blockIdx.x;               // b*128 + o
    const float* rp = g_attn + (size_t)row*KK;
    const float scale = 0.029462782549439483f;   // 1/sqrt(1152)
    const int tid = threadIdx.x;

    float m = -1e30f;
    for (int e = tid; e < KK; e += 256) m = fmaxf(m, rp[e]);
    red[tid] = m; __syncthreads();
    for (int s = 128; s > 0; s >>= 1) {
        if (tid < s) red[tid] = fmaxf(red[tid], red[tid + s]);
        __syncthreads();
    }
    m = red[0] * scale;
    __syncthreads();

    float sum = 0.f;
    for (int e = tid; e < KK; e += 256) sum += expf(rp[e]*scale - m);
    red[tid] = sum; __syncthreads();
    for (int s = 128; s > 0; s >>= 1) {
        if (tid < s) red[tid] += red[tid + s];
        __syncthreads();
    }
    float inv = 1.f / red[0];

    for (int e = tid; e < KK; e += 256) {
        float p = expf(rp[e]*scale - m) * inv;
        __nv_bfloat16 h = __float2bfloat16(p);
        g_kh[(size_t)row*KK + e] = h;
        g_kl[(size_t)row*KK + e] = __float2bfloat16(p - __bfloat162float(h));
    }
}

// ---------------- BN stats over av partitioned by (group, parity) ------------
__global__ __launch_bounds__(256) void stats_kernel() {
    const int g = blockIdx.x;   // 0..31
    const int b = blockIdx.y;   // 0..7
    const int tid = threadIdx.x;
    float s00=0,s01=0,s10=0,s11=0,q00=0,q01=0,q10=0,q11=0;
    for (int c = 0; c < 4; c++) {
        const float* p = g_av + ((size_t)b*CC_ + g*4 + c)*HW;
        for (int e = tid; e < HW/2; e += 256) {
            int y = e / 96;
            int x2 = (e - y*96) * 2;
            float v0 = p[y*WW + x2];
            float v1 = p[y*WW + x2 + 1];
            if (y & 1) { s10 += v0; q10 += v0*v0; s11 += v1; q11 += v1*v1; }
            else       { s00 += v0; q00 += v0*v0; s01 += v1; q01 += v1*v1; }
        }
    }
    __shared__ float red[256];
    float vals[8] = {s00, s01, s10, s11, q00, q01, q10, q11};
#pragma unroll
    for (int v = 0; v < 8; v++) {
        red[tid] = vals[v]; __syncthreads();
        for (int st = 128; st > 0; st >>= 1) {
            if (tid < st) red[tid] += red[tid + st];
            __syncthreads();
        }
        if (tid == 0) {
            int p2 = v & 3;
            if (v < 4) atomicAdd(&g_sum[g*4 + p2],   red[0]);
            else       atomicAdd(&g_sumsq[g*4 + p2], red[0]);
        }
        __syncthreads();
    }
}

__global__ void finalize_kernel() {
    int c = threadIdx.x;
    if (c < CC_) {
        float n = (float)STAT_N;
        float mean = g_sum[c] / n;
        float var  = g_sumsq[c] / n - mean*mean;
        g_mean[c] = mean;
        g_inv[c]  = NORM_SCALE * rsqrtf(var + EPSV);
    }
}

// ---------------- fused stack-gather + BN + residual epilogue ----------------
__global__ __launch_bounds__(256) void output_kernel(const float* __restrict__ x,
                                                     const float* __restrict__ mom_p,
                                                     float* __restrict__ out) {
    const float mom = *mom_p;
    for (size_t idx = (size_t)blockIdx.x*blockDim.x + threadIdx.x; idx < (size_t)TOT;
         idx += (size_t)gridDim.x*blockDim.x) {
        size_t b = idx / CHW;
        int r  = (int)(idx - b*CHW);
        int c2 = r / HW;
        int rr = r - c2*HW;
        int Y = rr / WW, X = rr - Y*WW;
        int i2 = (Y >= 96), j2 = (X >= 96);
        int ph = Y - i2*96, pw = X - j2*96;
        int sc = (c2 & ~3) | (i2*2 + j2);
        int sy = ph*2 + ((c2 >> 1) & 1);
        int sx = pw*2 + (c2 & 1);
        float v = g_av[((size_t)b*CC_ + sc)*HW + (size_t)sy*WW + sx];
        out[idx] = mom * x[idx] + (v - g_mean[c2]) * g_inv[c2];
    }
}

// ---------------- launch -----------------------------------------------------
extern "C" void kernel_launch(void* const* d_in, const int* in_sizes, int n_in,
                              void* d_out, int out_size) {
    const float* x   = (const float*)d_in[0];
    const float* w1  = (const float*)d_in[1];
    const float* w2  = (const float*)d_in[2];
    const float* w3  = (const float*)d_in[3];
    const float* mom = (const float*)d_in[4];
    float* out = (float*)d_out;

    __nv_bfloat16 *xh, *xl, *a3h, *a3l, *wh, *wl, *kh, *kl;
    float *a1, *a2, *av;
    cudaGetSymbolAddress((void**)&xh,  g_xh);
    cudaGetSymbolAddress((void**)&xl,  g_xl);
    cudaGetSymbolAddress((void**)&a1,  g_a1);
    cudaGetSymbolAddress((void**)&a2,  g_a2);
    cudaGetSymbolAddress((void**)&a3h, g_a3h);
    cudaGetSymbolAddress((void**)&a3l, g_a3l);
    cudaGetSymbolAddress((void**)&av,  g_av);
    cudaGetSymbolAddress((void**)&wh,  g_wh);
    cudaGetSymbolAddress((void**)&wl,  g_wl);
    cudaGetSymbolAddress((void**)&kh,  g_kh);
    cudaGetSymbolAddress((void**)&kl,  g_kl);

    zero_kernel<<<512, 256>>>();
    split_x_kernel<<<4096, 256>>>(x);
    split_w_kernel<<<dim3(144, 3), 256>>>(w1, w2, w3);

    dim3 cgrid(2, HH, BB);   // x-tile (96 px), row, batch
    conv_mma_kernel<<<cgrid, 256>>>(xh, xl, wh + 0*(size_t)CC_*KK, wl + 0*(size_t)CC_*KK,
                                    0, a1, nullptr, nullptr, 0);
    conv_mma_kernel<<<cgrid, 256>>>(xh, xl, wh + 1*(size_t)CC_*KK, wl + 1*(size_t)CC_*KK,
                                    0, a2, nullptr, nullptr, 0);
    conv_mma_kernel<<<cgrid, 256>>>(xh, xl, wh + 2*(size_t)CC_*KK, wl + 2*(size_t)CC_*KK,
                                    0, nullptr, a3h, a3l, 1);

    attn_gemm_kernel<<<dim3(4, 2, 64), 256>>>();
    softmax_kernel<<<BB*CC_, 256>>>();

    conv_mma_kernel<<<cgrid, 256>>>(a3h, a3l, kh, kl, (long)CC_*KK, av,
                                    nullptr, nullptr, 0);

    stats_kernel<<<dim3(32, 8), 256>>>();
    finalize_kernel<<<1, 128>>>();
    output_kernel<<<8192, 256>>>(x, mom, out);
}

// round 6
// speedup vs baseline: 1.5255x; 1.0431x over previous
#include <cuda_runtime.h>
#include <cuda_bf16.h>
#include <cstdint>
#include <cstdio>

#define BB 8
#define CC_ 128
#define HH 192
#define WW 192
#define HW (HH*WW)
#define CHW (CC_*HW)
#define TOT (BB*CHW)
#define KK 1152            // C*9
#define EPSV 1e-5f
#define NORM_SCALE 0.1816f
#define STAT_N (BB*4*(HH/2)*(WW/2))   // 294912

// ---------------- scratch (device globals; no allocations allowed) ------------
__device__ __align__(16) __nv_bfloat16 g_xh[TOT];
__device__ __align__(16) __nv_bfloat16 g_xl[TOT];
__device__ float g_a1[TOT];
__device__ float g_a2[TOT];
__device__ __align__(16) __nv_bfloat16 g_a3h[TOT];
__device__ __align__(16) __nv_bfloat16 g_a3l[TOT];
__device__ float g_av[TOT];
__device__ __align__(16) __nv_bfloat16 g_wh[3*CC_*KK];    // static weights, [w][o][k]
__device__ __align__(16) __nv_bfloat16 g_wl[3*CC_*KK];
__device__ __align__(16) __nv_bfloat16 g_kh[BB*CC_*KK];   // dynamic kernels, [b][o][k]
__device__ __align__(16) __nv_bfloat16 g_kl[BB*CC_*KK];
__device__ float g_attn[BB*CC_*KK];        // [b][o][i*9+h*3+w]
__device__ float g_sum[CC_];
__device__ float g_sumsq[CC_];
__device__ float g_mean[CC_];
__device__ float g_inv[CC_];

// ---------------- PTX helpers -------------------------------------------------
__device__ __forceinline__ uint32_t smem_u32(const void* p) {
    uint32_t a;
    asm("{ .reg .u64 t; cvta.to.shared.u64 t, %1; cvt.u32.u64 %0, t; }"
        : "=r"(a) : "l"(p));
    return a;
}

__device__ __forceinline__ void ldsm4(unsigned* r, uint32_t addr) {
    asm volatile("ldmatrix.sync.aligned.m8n8.x4.shared.b16 {%0,%1,%2,%3}, [%4];"
                 : "=r"(r[0]), "=r"(r[1]), "=r"(r[2]), "=r"(r[3]) : "r"(addr));
}
__device__ __forceinline__ void ldsm4t(unsigned* r, uint32_t addr) {
    asm volatile("ldmatrix.sync.aligned.m8n8.x4.trans.shared.b16 {%0,%1,%2,%3}, [%4];"
                 : "=r"(r[0]), "=r"(r[1]), "=r"(r[2]), "=r"(r[3]) : "r"(addr));
}
__device__ __forceinline__ void mma_bf16(float* d, const unsigned* a, const unsigned* b) {
    asm volatile(
        "mma.sync.aligned.m16n8k16.row.col.f32.bf16.bf16.f32 "
        "{%0,%1,%2,%3}, {%4,%5,%6,%7}, {%8,%9}, {%0,%1,%2,%3};"
        : "+f"(d[0]), "+f"(d[1]), "+f"(d[2]), "+f"(d[3])
        : "r"(a[0]), "r"(a[1]), "r"(a[2]), "r"(a[3]), "r"(b[0]), "r"(b[1]));
}
__device__ __forceinline__ void cp16(uint32_t dst, const void* src) {
    asm volatile("cp.async.cg.shared.global [%0], [%1], 16;"
                 :: "r"(dst), "l"(src) : "memory");
}
__device__ __forceinline__ void cp_commit() {
    asm volatile("cp.async.commit_group;" ::: "memory");
}
__device__ __forceinline__ void cp_wait_all() {
    asm volatile("cp.async.wait_group 0;" ::: "memory");
}

// ---------------- zero accumulators ------------------------------------------
__global__ void zero_kernel() {
    int n = BB*CC_*KK;
    for (int i = blockIdx.x*blockDim.x + threadIdx.x; i < n; i += gridDim.x*blockDim.x)
        g_attn[i] = 0.f;
    if (blockIdx.x == 0 && threadIdx.x < CC_) {
        g_sum[threadIdx.x] = 0.f;
        g_sumsq[threadIdx.x] = 0.f;
    }
}

// ---------------- split input x into bf16 hi/lo -------------------------------
__global__ void split_x_kernel(const float* __restrict__ x) {
    for (size_t i = (size_t)blockIdx.x*blockDim.x + threadIdx.x; i < (size_t)TOT;
         i += (size_t)gridDim.x*blockDim.x) {
        float v = x[i];
        __nv_bfloat16 h = __float2bfloat16(v);
        g_xh[i] = h;
        g_xl[i] = __float2bfloat16(v - __bfloat162float(h));
    }
}

// ---------------- split static weights into bf16 hi/lo (natural [o][k]) ------
__global__ void split_w_kernel(const float* __restrict__ w1,
                               const float* __restrict__ w2,
                               const float* __restrict__ w3) {
    const float* w = (blockIdx.y == 0) ? w1 : (blockIdx.y == 1) ? w2 : w3;
    int base = blockIdx.y * CC_ * KK;
    for (int e = blockIdx.x*blockDim.x + threadIdx.x; e < CC_*KK;
         e += gridDim.x*blockDim.x) {
        float v = w[e];
        __nv_bfloat16 h = __float2bfloat16(v);
        g_wh[base + e] = h;
        g_wl[base + e] = __float2bfloat16(v - __bfloat162float(h));
    }
}

// ---------------- bf16 tensor-core implicit-GEMM 3x3 conv ---------------------
// CTA: M=128 o x N=96 pixels, K=1152 in 36 chunks of 32. 8 warps = 4(m)x2(n).
// 2-stage smem pipeline: A via cp.async (issued during MMA), B via register
// prefetch (LDG during MMA of previous chunk, STS at loop top).
#define A_STRIDE 80     // 32 bf16 = 64B + 16B pad
#define B_STRIDE 208    // 96 bf16 = 192B + 16B pad
#define A_BYTES (128*A_STRIDE)          // 10240
#define B_BYTES (32*B_STRIDE)           // 6656
#define STG (2*A_BYTES + 2*B_BYTES)     // 33792: [Ah][Al][Bh][Bl]
#define SMEM_CONV (2*STG)               // 67584

__global__ __launch_bounds__(256, 2) void conv_mma_kernel(
    const __nv_bfloat16* __restrict__ inh, const __nv_bfloat16* __restrict__ inl,
    const __nv_bfloat16* __restrict__ wh_g, const __nv_bfloat16* __restrict__ wl_g,
    long wbstride, float* __restrict__ out1,
    __nv_bfloat16* __restrict__ oh, __nv_bfloat16* __restrict__ ol, int split_out)
{
    extern __shared__ __align__(16) unsigned char smem[];
    const int b  = blockIdx.z;
    const int y  = blockIdx.y;
    const int x0 = blockIdx.x * 96;
    const int tid = threadIdx.x;
    const int lane = tid & 31, wid = tid >> 5;
    const int wm = wid & 3, wn = wid >> 2;
    const uint32_t sb = smem_u32(smem);

    const __nv_bfloat16* wh = wh_g + (size_t)b*wbstride;
    const __nv_bfloat16* wl = wl_g + (size_t)b*wbstride;
    const __nv_bfloat16* inhb = inh + (size_t)b*CHW;
    const __nv_bfloat16* inlb = inl + (size_t)b*CHW;

    float acc[2][6][4];
#pragma unroll
    for (int mh = 0; mh < 2; mh++)
#pragma unroll
        for (int j = 0; j < 6; j++)
#pragma unroll
            for (int t = 0; t < 4; t++) acc[mh][j][t] = 0.f;

    __nv_bfloat162 breg[12];

    // ---- helpers (inlined by macro-style lambdas) ----
    auto cpA = [&](int c, int s) {
        uint32_t base = sb + s*STG;
#pragma unroll
        for (int i = 0; i < 4; i++) {
            int slot = tid + i*256;             // < 1024
            int hl = slot >> 9, rem = slot & 511;
            int o = rem >> 2, q = rem & 3;
            const __nv_bfloat16* src = (hl ? wl : wh) + (size_t)o*KK + c*32 + q*8;
            cp16(base + hl*A_BYTES + o*A_STRIDE + q*16, src);
        }
        cp_commit();
    };
    auto ldB = [&](int c) {
#pragma unroll
        for (int i = 0; i < 12; i++) {
            int slot = tid + i*256;             // < 3072
            int rowt = slot / 48, np = slot - rowt*48;
            int k = rowt & 31, hl = rowt >> 5;
            int kg = c*32 + k;
            int ic = kg / 9, rem = kg - ic*9;
            int r = rem / 3, dx = rem - r*3;
            int gy = y + r - 1;
            int gx = x0 + np*2 + dx - 1;
            __nv_bfloat162 pk;
            pk.x = __float2bfloat16(0.f); pk.y = pk.x;
            if ((unsigned)gy < HH) {
                const __nv_bfloat16* src = (hl ? inlb : inhb) + (size_t)ic*HW + gy*WW;
                if ((unsigned)gx < WW)     pk.x = src[gx];
                if ((unsigned)(gx+1) < WW) pk.y = src[gx+1];
            }
            breg[i] = pk;
        }
    };
    auto stB = [&](int s) {
        unsigned char* base = smem + s*STG + 2*A_BYTES;
#pragma unroll
        for (int i = 0; i < 12; i++) {
            int slot = tid + i*256;
            int rowt = slot / 48, np = slot - rowt*48;
            int k = rowt & 31, hl = rowt >> 5;
            *(__nv_bfloat162*)(base + hl*B_BYTES + k*B_STRIDE + np*4) = breg[i];
        }
    };

    // ---- prologue ----
    cpA(0, 0);
    ldB(0);

    for (int c = 0; c < 36; c++) {
        const int s = c & 1;
        stB(s);
        if (c < 35) ldB(c + 1);       // LDGs land during this chunk's MMA phase
        cp_wait_all();                // A(c) arrived
        __syncthreads();              // stage s fully visible; stage s^1 free
        if (c < 35) cpA(c + 1, s ^ 1);// copies overlap the MMA below

        const uint32_t Ah_s = sb + s*STG;
        const uint32_t Al_s = Ah_s + A_BYTES;
        const uint32_t Bh_s = Al_s + A_BYTES;
        const uint32_t Bl_s = Bh_s + B_BYTES;
#pragma unroll
        for (int st = 0; st < 2; st++) {
            unsigned Ah[2][4], Al[2][4], Bh[3][4], Bl[3][4];
#pragma unroll
            for (int mh = 0; mh < 2; mh++) {
                uint32_t off = (uint32_t)(wm*32 + mh*16 + (lane & 15))*A_STRIDE
                             + ((lane >> 4) << 4) + st*32;
                ldsm4(Ah[mh], Ah_s + off);
                ldsm4(Al[mh], Al_s + off);
            }
#pragma unroll
            for (int nf = 0; nf < 3; nf++) {
                uint32_t off = (uint32_t)(st*16 + (lane & 15))*B_STRIDE
                             + wn*96 + nf*32 + ((lane >> 4) << 4);
                ldsm4t(Bh[nf], Bh_s + off);
                ldsm4t(Bl[nf], Bl_s + off);
            }
#pragma unroll
            for (int mh = 0; mh < 2; mh++) {
#pragma unroll
                for (int j = 0; j < 6; j++) {
                    const unsigned* bh = &Bh[j >> 1][(j & 1)*2];
                    const unsigned* bl = &Bl[j >> 1][(j & 1)*2];
                    mma_bf16(acc[mh][j], Ah[mh], bh);
                    mma_bf16(acc[mh][j], Ah[mh], bl);
                    mma_bf16(acc[mh][j], Al[mh], bh);
                }
            }
        }
    }

    // ---- epilogue ----
#pragma unroll
    for (int mh = 0; mh < 2; mh++) {
        int o = wm*32 + mh*16 + (lane >> 2);
#pragma unroll
        for (int j = 0; j < 6; j++) {
            int x = x0 + wn*48 + j*8 + (lane & 3)*2;
            size_t i0 = ((size_t)b*CC_ + o)*HW + (size_t)y*WW + x;
            size_t i1 = i0 + (size_t)8*HW;
            if (!split_out) {
                *(float2*)(out1 + i0) = make_float2(acc[mh][j][0], acc[mh][j][1]);
                *(float2*)(out1 + i1) = make_float2(acc[mh][j][2], acc[mh][j][3]);
            } else {
                float v0 = acc[mh][j][0], v1 = acc[mh][j][1];
                float v2 = acc[mh][j][2], v3 = acc[mh][j][3];
                __nv_bfloat16 h0 = __float2bfloat16(v0), h1 = __float2bfloat16(v1);
                __nv_bfloat16 h2 = __float2bfloat16(v2), h3 = __float2bfloat16(v3);
                __nv_bfloat162 ph0; ph0.x = h0; ph0.y = h1;
                __nv_bfloat162 ph1; ph1.x = h2; ph1.y = h3;
                __nv_bfloat162 pl0;
                pl0.x = __float2bfloat16(v0 - __bfloat162float(h0));
                pl0.y = __float2bfloat16(v1 - __bfloat162float(h1));
                __nv_bfloat162 pl1;
                pl1.x = __float2bfloat16(v2 - __bfloat162float(h2));
                pl1.y = __float2bfloat16(v3 - __bfloat162float(h3));
                *(__nv_bfloat162*)(oh + i0) = ph0;
                *(__nv_bfloat162*)(oh + i1) = ph1;
                *(__nv_bfloat162*)(ol + i0) = pl0;
                *(__nv_bfloat162*)(ol + i1) = pl1;
            }
        }
    }
}

// ---------------- attention correlation GEMM (fp32 FFMA) ---------------------
__global__ __launch_bounds__(256) void attn_gemm_kernel() {
    __shared__ float a1s[96][34];
    __shared__ float a2s[64][97];
    const int ib = blockIdx.x * 32;
    const int ob = blockIdx.y * 64;
    const int b  = blockIdx.z >> 3;
    const int yb = (blockIdx.z & 7) * 24;
    const int tid = threadIdx.x;
    const int o0 = (tid & 15) * 4;
    const int i0 = (tid >> 4) * 2;
    const float* a1b = g_a1 + (size_t)b*CHW;
    const float* a2b = g_a2 + (size_t)b*CHW;

    float acc[3][3][2][4];
#pragma unroll
    for (int h = 0; h < 3; h++)
#pragma unroll
        for (int w = 0; w < 3; w++)
#pragma unroll
            for (int ii = 0; ii < 2; ii++)
#pragma unroll
                for (int j = 0; j < 4; j++) acc[h][w][ii][j] = 0.f;

    for (int y3 = 0; y3 < 8; y3++) {
#pragma unroll
        for (int h = 0; h < 3; h++) {
            const int y = yb + y3*3 + h;
#pragma unroll
            for (int xc = 0; xc < 192; xc += 96) {
                __syncthreads();
                for (int e = tid; e < 32*96; e += 256) {
                    int ii = e / 96, cc = e - ii*96;
                    a1s[cc][ii] = a1b[(size_t)(ib + ii)*HW + y*WW + xc + cc];
                }
                for (int e = tid; e < 64*96; e += 256) {
                    int oo = e / 96, cc = e - oo*96;
                    a2s[oo][cc] = a2b[(size_t)(ob + oo)*HW + y*WW + xc + cc];
                }
                __syncthreads();
#pragma unroll 2
                for (int x3 = 0; x3 < 32; x3++) {
#pragma unroll
                    for (int w = 0; w < 3; w++) {
                        const int cc = x3*3 + w;
                        float ai0 = a1s[cc][i0];
                        float ai1 = a1s[cc][i0 + 1];
#pragma unroll
                        for (int j = 0; j < 4; j++) {
                            float ao = a2s[o0 + j][cc];
                            acc[h][w][0][j] += ai0 * ao;
                            acc[h][w][1][j] += ai1 * ao;
                        }
                    }
                }
            }
        }
    }
#pragma unroll
    for (int h = 0; h < 3; h++)
#pragma unroll
        for (int w = 0; w < 3; w++)
#pragma unroll
            for (int ii = 0; ii < 2; ii++)
#pragma unroll
                for (int j = 0; j < 4; j++) {
                    atomicAdd(&g_attn[((size_t)b*CC_ + ob + o0 + j)*KK
                                      + (size_t)(ib + i0 + ii)*9 + h*3 + w],
                              acc[h][w][ii][j]);
                }
}

// ---------------- softmax; emits dynamic kernels as bf16 hi/lo [b][o][k] -----
__global__ __launch_bounds__(256) void softmax_kernel() {
    __shared__ float red[256];
    const int row = blockIdx.x;               // b*128 + o
    const float* rp = g_attn + (size_t)row*KK;
    const float scale = 0.029462782549439483f;   // 1/sqrt(1152)
    const int tid = threadIdx.x;

    float m = -1e30f;
    for (int e = tid; e < KK; e += 256) m = fmaxf(m, rp[e]);
    red[tid] = m; __syncthreads();
    for (int s = 128; s > 0; s >>= 1) {
        if (tid < s) red[tid] = fmaxf(red[tid], red[tid + s]);
        __syncthreads();
    }
    m = red[0] * scale;
    __syncthreads();

    float sum = 0.f;
    for (int e = tid; e < KK; e += 256) sum += expf(rp[e]*scale - m);
    red[tid] = sum; __syncthreads();
    for (int s = 128; s > 0; s >>= 1) {
        if (tid < s) red[tid] += red[tid + s];
        __syncthreads();
    }
    float inv = 1.f / red[0];

    for (int e = tid; e < KK; e += 256) {
        float p = expf(rp[e]*scale - m) * inv;
        __nv_bfloat16 h = __float2bfloat16(p);
        g_kh[(size_t)row*KK + e] = h;
        g_kl[(size_t)row*KK + e] = __float2bfloat16(p - __bfloat162float(h));
    }
}

// ---------------- BN stats over av partitioned by (group, parity) ------------
__global__ __launch_bounds__(256) void stats_kernel() {
    const int g = blockIdx.x;   // 0..31
    const int b = blockIdx.y;   // 0..7
    const int tid = threadIdx.x;
    float s00=0,s01=0,s10=0,s11=0,q00=0,q01=0,q10=0,q11=0;
    for (int c = 0; c < 4; c++) {
        const float* p = g_av + ((size_t)b*CC_ + g*4 + c)*HW;
        for (int e = tid; e < HW/2; e += 256) {
            int y = e / 96;
            int x2 = (e - y*96) * 2;
            float v0 = p[y*WW + x2];
            float v1 = p[y*WW + x2 + 1];
            if (y & 1) { s10 += v0; q10 += v0*v0; s11 += v1; q11 += v1*v1; }
            else       { s00 += v0; q00 += v0*v0; s01 += v1; q01 += v1*v1; }
        }
    }
    __shared__ float red[256];
    float vals[8] = {s00, s01, s10, s11, q00, q01, q10, q11};
#pragma unroll
    for (int v = 0; v < 8; v++) {
        red[tid] = vals[v]; __syncthreads();
        for (int st = 128; st > 0; st >>= 1) {
            if (tid < st) red[tid] += red[tid + st];
            __syncthreads();
        }
        if (tid == 0) {
            int p2 = v & 3;
            if (v < 4) atomicAdd(&g_sum[g*4 + p2],   red[0]);
            else       atomicAdd(&g_sumsq[g*4 + p2], red[0]);
        }
        __syncthreads();
    }
}

__global__ void finalize_kernel() {
    int c = threadIdx.x;
    if (c < CC_) {
        float n = (float)STAT_N;
        float mean = g_sum[c] / n;
        float var  = g_sumsq[c] / n - mean*mean;
        g_mean[c] = mean;
        g_inv[c]  = NORM_SCALE * rsqrtf(var + EPSV);
    }
}

// ---------------- fused stack-gather + BN + residual epilogue ----------------
__global__ __launch_bounds__(256) void output_kernel(const float* __restrict__ x,
                                                     const float* __restrict__ mom_p,
                                                     float* __restrict__ out) {
    const float mom = *mom_p;
    for (size_t idx = (size_t)blockIdx.x*blockDim.x + threadIdx.x; idx < (size_t)TOT;
         idx += (size_t)gridDim.x*blockDim.x) {
        size_t b = idx / CHW;
        int r  = (int)(idx - b*CHW);
        int c2 = r / HW;
        int rr = r - c2*HW;
        int Y = rr / WW, X = rr - Y*WW;
        int i2 = (Y >= 96), j2 = (X >= 96);
        int ph = Y - i2*96, pw = X - j2*96;
        int sc = (c2 & ~3) | (i2*2 + j2);
        int sy = ph*2 + ((c2 >> 1) & 1);
        int sx = pw*2 + (c2 & 1);
        float v = g_av[((size_t)b*CC_ + sc)*HW + (size_t)sy*WW + sx];
        out[idx] = mom * x[idx] + (v - g_mean[c2]) * g_inv[c2];
    }
}

// ---------------- launch -----------------------------------------------------
extern "C" void kernel_launch(void* const* d_in, const int* in_sizes, int n_in,
                              void* d_out, int out_size) {
    const float* x   = (const float*)d_in[0];
    const float* w1  = (const float*)d_in[1];
    const float* w2  = (const float*)d_in[2];
    const float* w3  = (const float*)d_in[3];
    const float* mom = (const float*)d_in[4];
    float* out = (float*)d_out;

    cudaFuncSetAttribute(conv_mma_kernel,
                         cudaFuncAttributeMaxDynamicSharedMemorySize, SMEM_CONV);

    __nv_bfloat16 *xh, *xl, *a3h, *a3l, *wh, *wl, *kh, *kl;
    float *a1, *a2, *av;
    cudaGetSymbolAddress((void**)&xh,  g_xh);
    cudaGetSymbolAddress((void**)&xl,  g_xl);
    cudaGetSymbolAddress((void**)&a1,  g_a1);
    cudaGetSymbolAddress((void**)&a2,  g_a2);
    cudaGetSymbolAddress((void**)&a3h, g_a3h);
    cudaGetSymbolAddress((void**)&a3l, g_a3l);
    cudaGetSymbolAddress((void**)&av,  g_av);
    cudaGetSymbolAddress((void**)&wh,  g_wh);
    cudaGetSymbolAddress((void**)&wl,  g_wl);
    cudaGetSymbolAddress((void**)&kh,  g_kh);
    cudaGetSymbolAddress((void**)&kl,  g_kl);

    zero_kernel<<<512, 256>>>();
    split_x_kernel<<<4096, 256>>>(x);
    split_w_kernel<<<dim3(144, 3), 256>>>(w1, w2, w3);

    dim3 cgrid(2, HH, BB);   // x-tile (96 px), row, batch
    conv_mma_kernel<<<cgrid, 256, SMEM_CONV>>>(xh, xl,
        wh + 0*(size_t)CC_*KK, wl + 0*(size_t)CC_*KK, 0, a1, nullptr, nullptr, 0);
    conv_mma_kernel<<<cgrid, 256, SMEM_CONV>>>(xh, xl,
        wh + 1*(size_t)CC_*KK, wl + 1*(size_t)CC_*KK, 0, a2, nullptr, nullptr, 0);
    conv_mma_kernel<<<cgrid, 256, SMEM_CONV>>>(xh, xl,
        wh + 2*(size_t)CC_*KK, wl + 2*(size_t)CC_*KK, 0, nullptr, a3h, a3l, 1);

    attn_gemm_kernel<<<dim3(4, 2, 64), 256>>>();
    softmax_kernel<<<BB*CC_, 256>>>();

    conv_mma_kernel<<<cgrid, 256, SMEM_CONV>>>(a3h, a3l, kh, kl, (long)CC_*KK, av,
                                               nullptr, nullptr, 0);

    stats_kernel<<<dim3(32, 8), 256>>>();
    finalize_kernel<<<1, 128>>>();
    output_kernel<<<8192, 256>>>(x, mom, out);
}

// round 7
// speedup vs baseline: 2.4000x; 1.5733x over previous
#include <cuda_runtime.h>
#include <cuda_bf16.h>
#include <cstdint>
#include <cstdio>

#define BB 8
#define CC_ 128
#define HH 192
#define WW 192
#define HW (HH*WW)
#define CHW (CC_*HW)
#define TOT (BB*CHW)
#define KK 1152            // C*9
#define EPSV 1e-5f
#define NORM_SCALE 0.1816f
#define STAT_N (BB*4*(HH/2)*(WW/2))   // 294912

// padded image geometry (1-px halo + alignment tail)
#define WP 200
#define HP 194
#define PLANE (HP*WP)          // 38800
#define PCHW (CC_*PLANE)       // 4966400
#define PTOT (BB*PCHW)         // 39731200

// ---------------- scratch (device globals; no allocations allowed) ------------
// padded inputs: _e = pixel at col x+1 (aligned for dx 0/2), _o = col x+2 (dx 1)
__device__ __align__(16) __nv_bfloat16 g_pxe_h[PTOT];
__device__ __align__(16) __nv_bfloat16 g_pxe_l[PTOT];
__device__ __align__(16) __nv_bfloat16 g_pxo_h[PTOT];
__device__ __align__(16) __nv_bfloat16 g_pxo_l[PTOT];
__device__ __align__(16) __nv_bfloat16 g_pae_h[PTOT];
__device__ __align__(16) __nv_bfloat16 g_pae_l[PTOT];
__device__ __align__(16) __nv_bfloat16 g_pao_h[PTOT];
__device__ __align__(16) __nv_bfloat16 g_pao_l[PTOT];
__device__ float g_a1[TOT];
__device__ float g_a2[TOT];
__device__ __align__(16) __nv_bfloat16 g_a3h[TOT];
__device__ __align__(16) __nv_bfloat16 g_a3l[TOT];
__device__ float g_av[TOT];
__device__ __align__(16) __nv_bfloat16 g_wh[3*CC_*KK];    // [w][o][knew], knew=(r*3+dx)*128+ic
__device__ __align__(16) __nv_bfloat16 g_wl[3*CC_*KK];
__device__ __align__(16) __nv_bfloat16 g_kh[BB*CC_*KK];   // [b][o][knew]
__device__ __align__(16) __nv_bfloat16 g_kl[BB*CC_*KK];
__device__ float g_attn[BB*CC_*KK];        // [b][o][i*9+h*3+w]
__device__ float g_sum[CC_];
__device__ float g_sumsq[CC_];
__device__ float g_mean[CC_];
__device__ float g_inv[CC_];

// ---------------- PTX helpers -------------------------------------------------
__device__ __forceinline__ uint32_t smem_u32(const void* p) {
    uint32_t a;
    asm("{ .reg .u64 t; cvta.to.shared.u64 t, %1; cvt.u32.u64 %0, t; }"
        : "=r"(a) : "l"(p));
    return a;
}
__device__ __forceinline__ void ldsm4(unsigned* r, uint32_t addr) {
    asm volatile("ldmatrix.sync.aligned.m8n8.x4.shared.b16 {%0,%1,%2,%3}, [%4];"
                 : "=r"(r[0]), "=r"(r[1]), "=r"(r[2]), "=r"(r[3]) : "r"(addr));
}
__device__ __forceinline__ void ldsm4t(unsigned* r, uint32_t addr) {
    asm volatile("ldmatrix.sync.aligned.m8n8.x4.trans.shared.b16 {%0,%1,%2,%3}, [%4];"
                 : "=r"(r[0]), "=r"(r[1]), "=r"(r[2]), "=r"(r[3]) : "r"(addr));
}
__device__ __forceinline__ void mma_bf16(float* d, const unsigned* a, const unsigned* b) {
    asm volatile(
        "mma.sync.aligned.m16n8k16.row.col.f32.bf16.bf16.f32 "
        "{%0,%1,%2,%3}, {%4,%5,%6,%7}, {%8,%9}, {%0,%1,%2,%3};"
        : "+f"(d[0]), "+f"(d[1]), "+f"(d[2]), "+f"(d[3])
        : "r"(a[0]), "r"(a[1]), "r"(a[2]), "r"(a[3]), "r"(b[0]), "r"(b[1]));
}
__device__ __forceinline__ void cp16(uint32_t dst, const void* src) {
    asm volatile("cp.async.cg.shared.global [%0], [%1], 16;"
                 :: "r"(dst), "l"(src) : "memory");
}
__device__ __forceinline__ void cp4(uint32_t dst, const void* src) {
    asm volatile("cp.async.ca.shared.global [%0], [%1], 4;"
                 :: "r"(dst), "l"(src) : "memory");
}
__device__ __forceinline__ void cp_commit() {
    asm volatile("cp.async.commit_group;" ::: "memory");
}
__device__ __forceinline__ void cp_wait1() {
    asm volatile("cp.async.wait_group 1;" ::: "memory");
}
__device__ __forceinline__ void cp_wait0() {
    asm volatile("cp.async.wait_group 0;" ::: "memory");
}

// ---------------- zero accumulators ------------------------------------------
__global__ void zero_kernel() {
    int n = BB*CC_*KK;
    for (int i = blockIdx.x*blockDim.x + threadIdx.x; i < n; i += gridDim.x*blockDim.x)
        g_attn[i] = 0.f;
    if (blockIdx.x == 0 && threadIdx.x < CC_) {
        g_sum[threadIdx.x] = 0.f;
        g_sumsq[threadIdx.x] = 0.f;
    }
}

// ---------------- split x into padded bf16 hi/lo copies (aligned + shifted) ---
__global__ void split_x_pad_kernel(const float* __restrict__ x) {
    for (size_t idx = (size_t)blockIdx.x*blockDim.x + threadIdx.x; idx < (size_t)PTOT;
         idx += (size_t)gridDim.x*blockDim.x) {
        size_t bc = idx / PLANE;
        int p  = (int)(idx - bc*PLANE);
        int py = p / WP, px = p - py*WP;
        int yy = py - 1;
        float va = 0.f, vs = 0.f;
        if ((unsigned)yy < HH) {
            const float* row = x + bc*HW + (size_t)yy*WW;
            int xa = px - 1, xs = px - 2;
            if ((unsigned)xa < WW) va = row[xa];
            if ((unsigned)xs < WW) vs = row[xs];
        }
        __nv_bfloat16 ha = __float2bfloat16(va);
        g_pxe_h[idx] = ha;
        g_pxe_l[idx] = __float2bfloat16(va - __bfloat162float(ha));
        __nv_bfloat16 hs = __float2bfloat16(vs);
        g_pxo_h[idx] = hs;
        g_pxo_l[idx] = __float2bfloat16(vs - __bfloat162float(hs));
    }
}

// ---------------- pad a3 hi/lo into aligned + shifted copies ------------------
__global__ void pad_a3_kernel() {
    for (size_t idx = (size_t)blockIdx.x*blockDim.x + threadIdx.x; idx < (size_t)PTOT;
         idx += (size_t)gridDim.x*blockDim.x) {
        size_t bc = idx / PLANE;
        int p  = (int)(idx - bc*PLANE);
        int py = p / WP, px = p - py*WP;
        int yy = py - 1;
        __nv_bfloat16 z = __float2bfloat16(0.f);
        __nv_bfloat16 ha = z, la = z, hs = z, ls = z;
        if ((unsigned)yy < HH) {
            size_t rbase = bc*HW + (size_t)yy*WW;
            int xa = px - 1, xs = px - 2;
            if ((unsigned)xa < WW) { ha = g_a3h[rbase + xa]; la = g_a3l[rbase + xa]; }
            if ((unsigned)xs < WW) { hs = g_a3h[rbase + xs]; ls = g_a3l[rbase + xs]; }
        }
        g_pae_h[idx] = ha; g_pae_l[idx] = la;
        g_pao_h[idx] = hs; g_pao_l[idx] = ls;
    }
}

// ---------------- split static weights (permuted k: knew=(r*3+dx)*128+ic) -----
__global__ void split_w_kernel(const float* __restrict__ w1,
                               const float* __restrict__ w2,
                               const float* __restrict__ w3) {
    const float* w = (blockIdx.y == 0) ? w1 : (blockIdx.y == 1) ? w2 : w3;
    int base = blockIdx.y * CC_ * KK;
    for (int e = blockIdx.x*blockDim.x + threadIdx.x; e < CC_*KK;
         e += gridDim.x*blockDim.x) {
        int o = e / KK, knew = e - o*KK;
        int rr = knew >> 7, ic = knew & 127;
        float v = w[(size_t)o*KK + ic*9 + rr];
        __nv_bfloat16 h = __float2bfloat16(v);
        g_wh[base + e] = h;
        g_wl[base + e] = __float2bfloat16(v - __bfloat162float(h));
    }
}

// ---------------- bf16 tensor-core implicit-GEMM 3x3 conv ---------------------
// CTA: M=128 o x N=96 px. K=1152 in 36 chunks of 32, (r,dx)-major so each chunk
// is one kernel offset: B build = 32 contiguous aligned segments via cp.async.
// 3-stage cp.async pipeline, one barrier per chunk.
#define A_STRIDE 80     // 32 bf16 + 16B pad
#define B_STRIDE 208    // 96 bf16 + 16B pad
#define A_BYTES (128*A_STRIDE)          // 10240
#define B_BYTES (32*B_STRIDE)           // 6656
#define STG (2*A_BYTES + 2*B_BYTES)     // 33792
#define SMEM_CONV (3*STG)               // 101376

__global__ __launch_bounds__(256, 2) void conv_mma_kernel(
    const __nv_bfloat16* __restrict__ pe_h, const __nv_bfloat16* __restrict__ pe_l,
    const __nv_bfloat16* __restrict__ po_h, const __nv_bfloat16* __restrict__ po_l,
    const __nv_bfloat16* __restrict__ wh_g, const __nv_bfloat16* __restrict__ wl_g,
    long wbstride, float* __restrict__ out1,
    __nv_bfloat16* __restrict__ oh, __nv_bfloat16* __restrict__ ol, int split_out)
{
    extern __shared__ __align__(16) unsigned char smem[];
    const int b  = blockIdx.z;
    const int y  = blockIdx.y;
    const int x0 = blockIdx.x * 96;
    const int tid = threadIdx.x;
    const int lane = tid & 31, wid = tid >> 5;
    const int wm = wid & 3, wn = wid >> 2;
    const uint32_t sb = smem_u32(smem);

    const __nv_bfloat16* peh = pe_h + (size_t)b*PCHW;
    const __nv_bfloat16* pel = pe_l + (size_t)b*PCHW;
    const __nv_bfloat16* poh = po_h + (size_t)b*PCHW;
    const __nv_bfloat16* pol = po_l + (size_t)b*PCHW;
    const __nv_bfloat16* wh = wh_g + (size_t)b*wbstride;
    const __nv_bfloat16* wl = wl_g + (size_t)b*wbstride;

    // per-thread slot constants
    // B: slots i and i+6 share geometry (hl = i>=6)
    int bsrc[6], bdst[6];
#pragma unroll
    for (int i = 0; i < 6; i++) {
        int slot = tid + i*256;              // < 1536
        int rowt = slot / 48, np = slot - rowt*48;   // rowt < 32
        bsrc[i] = rowt*PLANE + np*2;
        bdst[i] = rowt*B_STRIDE + np*4;
    }
    // A: slots 0,1 hi; 2,3 lo
    int adst[4], aoff[4];
#pragma unroll
    for (int i = 0; i < 4; i++) {
        int slot = tid + i*256;
        int rem = slot & 511;
        int o = rem >> 2, qq = rem & 3;
        adst[i] = (slot >> 9)*A_BYTES + o*A_STRIDE + qq*16;
        aoff[i] = o*KK + qq*8;
    }

    float acc[2][6][4];
#pragma unroll
    for (int mh = 0; mh < 2; mh++)
#pragma unroll
        for (int j = 0; j < 6; j++)
#pragma unroll
            for (int t = 0; t < 4; t++) acc[mh][j][t] = 0.f;

    auto loadAB = [&](int c) {
        const uint32_t stg = sb + (c % 3)*STG;
        const int kofs = c*32;
#pragma unroll
        for (int i = 0; i < 2; i++) cp16(stg + adst[i], wh + aoff[i] + kofs);
#pragma unroll
        for (int i = 2; i < 4; i++) cp16(stg + adst[i], wl + aoff[i] + kofs);
        int r = c / 12, t = c - r*12;
        int dx = t >> 2, q = t & 3;
        int ibase = q*32*PLANE + (y + r)*WP + x0 + dx + (dx == 1);
        const __nv_bfloat16* hp = ((dx == 1) ? poh : peh) + ibase;
        const __nv_bfloat16* lp = ((dx == 1) ? pol : pel) + ibase;
        const uint32_t bb = stg + 2*A_BYTES;
#pragma unroll
        for (int i = 0; i < 6; i++) {
            cp4(bb + bdst[i],           hp + bsrc[i]);
            cp4(bb + B_BYTES + bdst[i], lp + bsrc[i]);
        }
        cp_commit();
    };

    loadAB(0);
    loadAB(1);

    for (int c = 0; c < 36; c++) {
        if (c < 34) cp_wait1(); else cp_wait0();
        __syncthreads();
        if (c < 34) loadAB(c + 2);

        const uint32_t stg = sb + (c % 3)*STG;
        const uint32_t Ah_s = stg;
        const uint32_t Al_s = stg + A_BYTES;
        const uint32_t Bh_s = stg + 2*A_BYTES;
        const uint32_t Bl_s = Bh_s + B_BYTES;
#pragma unroll
        for (int st = 0; st < 2; st++) {
            unsigned Ah[2][4], Al[2][4], Bh[3][4], Bl[3][4];
#pragma unroll
            for (int mh = 0; mh < 2; mh++) {
                uint32_t off = (uint32_t)(wm*32 + mh*16 + (lane & 15))*A_STRIDE
                             + ((lane >> 4) << 4) + st*32;
                ldsm4(Ah[mh], Ah_s + off);
                ldsm4(Al[mh], Al_s + off);
            }
#pragma unroll
            for (int nf = 0; nf < 3; nf++) {
                uint32_t off = (uint32_t)(st*16 + (lane & 15))*B_STRIDE
                             + wn*96 + nf*32 + ((lane >> 4) << 4);
                ldsm4t(Bh[nf], Bh_s + off);
                ldsm4t(Bl[nf], Bl_s + off);
            }
#pragma unroll
            for (int mh = 0; mh < 2; mh++) {
#pragma unroll
                for (int j = 0; j < 6; j++) {
                    const unsigned* bh = &Bh[j >> 1][(j & 1)*2];
                    const unsigned* bl = &Bl[j >> 1][(j & 1)*2];
                    mma_bf16(acc[mh][j], Ah[mh], bh);
                    mma_bf16(acc[mh][j], Ah[mh], bl);
                    mma_bf16(acc[mh][j], Al[mh], bh);
                }
            }
        }
    }

    // ---- epilogue ----
#pragma unroll
    for (int mh = 0; mh < 2; mh++) {
        int o = wm*32 + mh*16 + (lane >> 2);
#pragma unroll
        for (int j = 0; j < 6; j++) {
            int x = x0 + wn*48 + j*8 + (lane & 3)*2;
            size_t i0 = ((size_t)b*CC_ + o)*HW + (size_t)y*WW + x;
            size_t i1 = i0 + (size_t)8*HW;
            if (!split_out) {
                *(float2*)(out1 + i0) = make_float2(acc[mh][j][0], acc[mh][j][1]);
                *(float2*)(out1 + i1) = make_float2(acc[mh][j][2], acc[mh][j][3]);
            } else {
                float v0 = acc[mh][j][0], v1 = acc[mh][j][1];
                float v2 = acc[mh][j][2], v3 = acc[mh][j][3];
                __nv_bfloat16 h0 = __float2bfloat16(v0), h1 = __float2bfloat16(v1);
                __nv_bfloat16 h2 = __float2bfloat16(v2), h3 = __float2bfloat16(v3);
                __nv_bfloat162 ph0; ph0.x = h0; ph0.y = h1;
                __nv_bfloat162 ph1; ph1.x = h2; ph1.y = h3;
                __nv_bfloat162 pl0;
                pl0.x = __float2bfloat16(v0 - __bfloat162float(h0));
                pl0.y = __float2bfloat16(v1 - __bfloat162float(h1));
                __nv_bfloat162 pl1;
                pl1.x = __float2bfloat16(v2 - __bfloat162float(h2));
                pl1.y = __float2bfloat16(v3 - __bfloat162float(h3));
                *(__nv_bfloat162*)(oh + i0) = ph0;
                *(__nv_bfloat162*)(oh + i1) = ph1;
                *(__nv_bfloat162*)(ol + i0) = pl0;
                *(__nv_bfloat162*)(ol + i1) = pl1;
            }
        }
    }
}

// ---------------- attention correlation GEMM (fp32 FFMA) ---------------------
__global__ __launch_bounds__(256) void attn_gemm_kernel() {
    __shared__ float a1s[96][34];
    __shared__ float a2s[64][97];
    const int ib = blockIdx.x * 32;
    const int ob = blockIdx.y * 64;
    const int b  = blockIdx.z >> 3;
    const int yb = (blockIdx.z & 7) * 24;
    const int tid = threadIdx.x;
    const int o0 = (tid & 15) * 4;
    const int i0 = (tid >> 4) * 2;
    const float* a1b = g_a1 + (size_t)b*CHW;
    const float* a2b = g_a2 + (size_t)b*CHW;

    float acc[3][3][2][4];
#pragma unroll
    for (int h = 0; h < 3; h++)
#pragma unroll
        for (int w = 0; w < 3; w++)
#pragma unroll
            for (int ii = 0; ii < 2; ii++)
#pragma unroll
                for (int j = 0; j < 4; j++) acc[h][w][ii][j] = 0.f;

    for (int y3 = 0; y3 < 8; y3++) {
#pragma unroll
        for (int h = 0; h < 3; h++) {
            const int y = yb + y3*3 + h;
#pragma unroll
            for (int xc = 0; xc < 192; xc += 96) {
                __syncthreads();
                for (int e = tid; e < 32*96; e += 256) {
                    int ii = e / 96, cc = e - ii*96;
                    a1s[cc][ii] = a1b[(size_t)(ib + ii)*HW + y*WW + xc + cc];
                }
                for (int e = tid; e < 64*96; e += 256) {
                    int oo = e / 96, cc = e - oo*96;
                    a2s[oo][cc] = a2b[(size_t)(ob + oo)*HW + y*WW + xc + cc];
                }
                __syncthreads();
#pragma unroll 2
                for (int x3 = 0; x3 < 32; x3++) {
#pragma unroll
                    for (int w = 0; w < 3; w++) {
                        const int cc = x3*3 + w;
                        float ai0 = a1s[cc][i0];
                        float ai1 = a1s[cc][i0 + 1];
#pragma unroll
                        for (int j = 0; j < 4; j++) {
                            float ao = a2s[o0 + j][cc];
                            acc[h][w][0][j] += ai0 * ao;
                            acc[h][w][1][j] += ai1 * ao;
                        }
                    }
                }
            }
        }
    }
#pragma unroll
    for (int h = 0; h < 3; h++)
#pragma unroll
        for (int w = 0; w < 3; w++)
#pragma unroll
            for (int ii = 0; ii < 2; ii++)
#pragma unroll
                for (int j = 0; j < 4; j++) {
                    atomicAdd(&g_attn[((size_t)b*CC_ + ob + o0 + j)*KK
                                      + (size_t)(ib + i0 + ii)*9 + h*3 + w],
                              acc[h][w][ii][j]);
                }
}

// ---------------- softmax; emits dynamic kernels as bf16 hi/lo, permuted k ----
__global__ __launch_bounds__(256) void softmax_kernel() {
    __shared__ float red[256];
    const int row = blockIdx.x;               // b*128 + o
    const float* rp = g_attn + (size_t)row*KK;
    const float scale = 0.029462782549439483f;   // 1/sqrt(1152)
    const int tid = threadIdx.x;

    float m = -1e30f;
    for (int e = tid; e < KK; e += 256) m = fmaxf(m, rp[e]);
    red[tid] = m; __syncthreads();
    for (int s = 128; s > 0; s >>= 1) {
        if (tid < s) red[tid] = fmaxf(red[tid], red[tid + s]);
        __syncthreads();
    }
    m = red[0] * scale;
    __syncthreads();

    float sum = 0.f;
    for (int e = tid; e < KK; e += 256) sum += expf(rp[e]*scale - m);
    red[tid] = sum; __syncthreads();
    for (int s = 128; s > 0; s >>= 1) {
        if (tid < s) red[tid] += red[tid + s];
        __syncthreads();
    }
    float inv = 1.f / red[0];

    for (int e = tid; e < KK; e += 256) {
        float p = expf(rp[e]*scale - m) * inv;
        int i = e / 9, rr = e - i*9;
        int knew = rr*128 + i;
        __nv_bfloat16 h = __float2bfloat16(p);
        g_kh[(size_t)row*KK + knew] = h;
        g_kl[(size_t)row*KK + knew] = __float2bfloat16(p - __bfloat162float(h));
    }
}

// ---------------- BN stats over av partitioned by (group, parity) ------------
__global__ __launch_bounds__(256) void stats_kernel() {
    const int g = blockIdx.x;   // 0..31
    const int b = blockIdx.y;   // 0..7
    const int tid = threadIdx.x;
    float s00=0,s01=0,s10=0,s11=0,q00=0,q01=0,q10=0,q11=0;
    for (int c = 0; c < 4; c++) {
        const float* p = g_av + ((size_t)b*CC_ + g*4 + c)*HW;
        for (int e = tid; e < HW/2; e += 256) {
            int y = e / 96;
            int x2 = (e - y*96) * 2;
            float v0 = p[y*WW + x2];
            float v1 = p[y*WW + x2 + 1];
            if (y & 1) { s10 += v0; q10 += v0*v0; s11 += v1; q11 += v1*v1; }
            else       { s00 += v0; q00 += v0*v0; s01 += v1; q01 += v1*v1; }
        }
    }
    __shared__ float red[256];
    float vals[8] = {s00, s01, s10, s11, q00, q01, q10, q11};
#pragma unroll
    for (int v = 0; v < 8; v++) {
        red[tid] = vals[v]; __syncthreads();
        for (int st = 128; st > 0; st >>= 1) {
            if (tid < st) red[tid] += red[tid + st];
            __syncthreads();
        }
        if (tid == 0) {
            int p2 = v & 3;
            if (v < 4) atomicAdd(&g_sum[g*4 + p2],   red[0]);
            else       atomicAdd(&g_sumsq[g*4 + p2], red[0]);
        }
        __syncthreads();
    }
}

__global__ void finalize_kernel() {
    int c = threadIdx.x;
    if (c < CC_) {
        float n = (float)STAT_N;
        float mean = g_sum[c] / n;
        float var  = g_sumsq[c] / n - mean*mean;
        g_mean[c] = mean;
        g_inv[c]  = NORM_SCALE * rsqrtf(var + EPSV);
    }
}

// ---------------- fused stack-gather + BN + residual epilogue ----------------
__global__ __launch_bounds__(256) void output_kernel(const float* __restrict__ x,
                                                     const float* __restrict__ mom_p,
                                                     float* __restrict__ out) {
    const float mom = *mom_p;
    for (size_t idx = (size_t)blockIdx.x*blockDim.x + threadIdx.x; idx < (size_t)TOT;
         idx += (size_t)gridDim.x*blockDim.x) {
        size_t b = idx / CHW;
        int r  = (int)(idx - b*CHW);
        int c2 = r / HW;
        int rr = r - c2*HW;
        int Y = rr / WW, X = rr - Y*WW;
        int i2 = (Y >= 96), j2 = (X >= 96);
        int ph = Y - i2*96, pw = X - j2*96;
        int sc = (c2 & ~3) | (i2*2 + j2);
        int sy = ph*2 + ((c2 >> 1) & 1);
        int sx = pw*2 + (c2 & 1);
        float v = g_av[((size_t)b*CC_ + sc)*HW + (size_t)sy*WW + sx];
        out[idx] = mom * x[idx] + (v - g_mean[c2]) * g_inv[c2];
    }
}

// ---------------- launch -----------------------------------------------------
extern "C" void kernel_launch(void* const* d_in, const int* in_sizes, int n_in,
                              void* d_out, int out_size) {
    const float* x   = (const float*)d_in[0];
    const float* w1  = (const float*)d_in[1];
    const float* w2  = (const float*)d_in[2];
    const float* w3  = (const float*)d_in[3];
    const float* mom = (const float*)d_in[4];
    float* out = (float*)d_out;

    cudaFuncSetAttribute(conv_mma_kernel,
                         cudaFuncAttributeMaxDynamicSharedMemorySize, SMEM_CONV);

    __nv_bfloat16 *pxe_h, *pxe_l, *pxo_h, *pxo_l;
    __nv_bfloat16 *pae_h, *pae_l, *pao_h, *pao_l;
    __nv_bfloat16 *a3h, *a3l, *wh, *wl, *kh, *kl;
    float *a1, *a2, *av;
    cudaGetSymbolAddress((void**)&pxe_h, g_pxe_h);
    cudaGetSymbolAddress((void**)&pxe_l, g_pxe_l);
    cudaGetSymbolAddress((void**)&pxo_h, g_pxo_h);
    cudaGetSymbolAddress((void**)&pxo_l, g_pxo_l);
    cudaGetSymbolAddress((void**)&pae_h, g_pae_h);
    cudaGetSymbolAddress((void**)&pae_l, g_pae_l);
    cudaGetSymbolAddress((void**)&pao_h, g_pao_h);
    cudaGetSymbolAddress((void**)&pao_l, g_pao_l);
    cudaGetSymbolAddress((void**)&a1,  g_a1);
    cudaGetSymbolAddress((void**)&a2,  g_a2);
    cudaGetSymbolAddress((void**)&a3h, g_a3h);
    cudaGetSymbolAddress((void**)&a3l, g_a3l);
    cudaGetSymbolAddress((void**)&av,  g_av);
    cudaGetSymbolAddress((void**)&wh,  g_wh);
    cudaGetSymbolAddress((void**)&wl,  g_wl);
    cudaGetSymbolAddress((void**)&kh,  g_kh);
    cudaGetSymbolAddress((void**)&kl,  g_kl);

    zero_kernel<<<512, 256>>>();
    split_x_pad_kernel<<<8192, 256>>>(x);
    split_w_kernel<<<dim3(144, 3), 256>>>(w1, w2, w3);

    dim3 cgrid(2, HH, BB);   // x-tile (96 px), row, batch
    conv_mma_kernel<<<cgrid, 256, SMEM_CONV>>>(pxe_h, pxe_l, pxo_h, pxo_l,
        wh + 0*(size_t)CC_*KK, wl + 0*(size_t)CC_*KK, 0, a1, nullptr, nullptr, 0);
    conv_mma_kernel<<<cgrid, 256, SMEM_CONV>>>(pxe_h, pxe_l, pxo_h, pxo_l,
        wh + 1*(size_t)CC_*KK, wl + 1*(size_t)CC_*KK, 0, a2, nullptr, nullptr, 0);
    conv_mma_kernel<<<cgrid, 256, SMEM_CONV>>>(pxe_h, pxe_l, pxo_h, pxo_l,
        wh + 2*(size_t)CC_*KK, wl + 2*(size_t)CC_*KK, 0, nullptr, a3h, a3l, 1);

    pad_a3_kernel<<<8192, 256>>>();
    attn_gemm_kernel<<<dim3(4, 2, 64), 256>>>();
    softmax_kernel<<<BB*CC_, 256>>>();

    conv_mma_kernel<<<cgrid, 256, SMEM_CONV>>>(pae_h, pae_l, pao_h, pao_l,
        kh, kl, (long)CC_*KK, av, nullptr, nullptr, 0);

    stats_kernel<<<dim3(32, 8), 256>>>();
    finalize_kernel<<<1, 128>>>();
    output_kernel<<<8192, 256>>>(x, mom, out);
}